// round 2
// baseline (speedup 1.0000x reference)
#include <cuda_runtime.h>

// Problem constants
#define NBT   96      // B*T
#define NSEQ  512     // N
#define DMODEL 64
#define KH    8
#define HD    8
#define TOKENS (NBT * NSEQ)   // 49152

typedef unsigned long long u64;

// Scratch: q row-major [h][bt][n][d]; k,v TRANSPOSED [h][bt][d][n]; att [tok][64]
__device__ float g_q[KH * NBT * NSEQ * HD];
__device__ float g_k[KH * NBT * NSEQ * HD];
__device__ float g_v[KH * NBT * NSEQ * HD];
__device__ float g_att[TOKENS * DMODEL];

// ---------------- f32x2 packed-pair primitives (FFMA2 path) ----------------
__device__ __forceinline__ u64 pk2(float a, float b) {
    u64 r; asm("mov.b64 %0, {%1,%2};" : "=l"(r) : "f"(a), "f"(b)); return r;
}
__device__ __forceinline__ void upk(u64 v, float& a, float& b) {
    asm("mov.b64 {%0,%1}, %2;" : "=f"(a), "=f"(b) : "l"(v));
}
__device__ __forceinline__ u64 f2fma(u64 a, u64 b, u64 c) {
    u64 d; asm("fma.rn.f32x2 %0, %1, %2, %3;" : "=l"(d) : "l"(a), "l"(b), "l"(c)); return d;
}
__device__ __forceinline__ u64 f2add(u64 a, u64 b) {
    u64 d; asm("add.rn.f32x2 %0, %1, %2;" : "=l"(d) : "l"(a), "l"(b)); return d;
}
__device__ __forceinline__ u64 f2mul(u64 a, u64 b) {
    u64 d; asm("mul.rn.f32x2 %0, %1, %2;" : "=l"(d) : "l"(a), "l"(b)); return d;
}

// Packed exp of two fp32 lanes. e^x = 2^r * (1 + g*P(g)), |g|<=0.347,
// P deg-4 Taylor (rel err ~2.4e-6). 10 fma-pipe ops for TWO exps.
__device__ __forceinline__ u64 fexp2pk(u64 x) {
    const u64 LOG2E  = pk2(1.4426950408889634f, 1.4426950408889634f);
    const u64 MAGIC  = pk2(12582912.0f, 12582912.0f);
    const u64 NMAGIC = pk2(-12582912.0f, -12582912.0f);
    const u64 NL2HI  = pk2(-0.693145751953125f, -0.693145751953125f);
    const u64 NL2LO  = pk2(-1.428606765330187e-06f, -1.428606765330187e-06f);
    const u64 P120   = pk2(8.3333333e-3f, 8.3333333e-3f);   // 1/120
    const u64 P24    = pk2(4.1666667e-2f, 4.1666667e-2f);   // 1/24
    const u64 P6     = pk2(1.6666667e-1f, 1.6666667e-1f);   // 1/6
    const u64 P2     = pk2(0.5f, 0.5f);
    const u64 ONE    = pk2(1.0f, 1.0f);

    u64 t = f2fma(x, LOG2E, MAGIC);
    float ta, tb; upk(t, ta, tb);
    unsigned ea = __float_as_uint(ta) * 8388608u + 0x3f800000u;  // (n<<23)+bias
    unsigned eb = __float_as_uint(tb) * 8388608u + 0x3f800000u;
    u64 r = f2add(t, NMAGIC);
    u64 g = f2fma(r, NL2HI, x);
    g = f2fma(r, NL2LO, g);
    u64 p = f2fma(P120, g, P24);
    p = f2fma(p, g, P6);
    p = f2fma(p, g, P2);
    p = f2fma(p, g, ONE);
    u64 eg = f2fma(g, p, ONE);
    u64 sc = pk2(__uint_as_float(ea), __uint_as_float(eb));
    return f2mul(eg, sc);
}

// ---------------------------------------------------------------------------
// Kernel 1: fused QKV projection, k-packed f32x2.
// H=[X|STE] (49152x128); out = relu(H@W+b). q row-major head layout;
// k,v written TRANSPOSED [h][bt][d][n] for the attention kernel.
// grid (768, 3), 256 threads, 64x64 tile, 4x4 per thread, k packed in lanes.
// ---------------------------------------------------------------------------
__global__ __launch_bounds__(256) void qkv_kernel(
    const float* __restrict__ X, const float* __restrict__ STE,
    const float* __restrict__ W7, const float* __restrict__ b7,
    const float* __restrict__ W8, const float* __restrict__ b8,
    const float* __restrict__ W9, const float* __restrict__ b9)
{
    __shared__ __align__(16) float sA[64][32];    // [row][k]
    __shared__ __align__(16) float sBT[64][36];   // [col][k], padded

    const int mat = blockIdx.y;
    const float* W  = (mat == 0) ? W7 : (mat == 1) ? W8 : W9;
    const float* bv = (mat == 0) ? b7 : (mat == 1) ? b8 : b9;
    float* gout     = (mat == 0) ? g_q : (mat == 1) ? g_k : g_v;

    const int row0 = blockIdx.x * 64;
    const int bt   = row0 >> 9;
    const int n0b  = row0 & 511;
    const int tid  = threadIdx.x;
    const int tx   = tid & 15;     // 4 cols each
    const int ty   = tid >> 4;     // 4 rows each

    u64 c[4][4];
    #pragma unroll
    for (int i = 0; i < 4; i++)
        #pragma unroll
        for (int j = 0; j < 4; j++) c[i][j] = 0ull;

    #pragma unroll 1
    for (int kc = 0; kc < 4; kc++) {
        const float* src = (kc < 2) ? X : STE;
        const int kbase = (kc & 1) * 32;
        const int kglob = kc * 32;

        #pragma unroll
        for (int e = 0; e < 8; e++) {
            int idx = e * 256 + tid;
            int rr = idx >> 5, kk = idx & 31;
            sA[rr][kk] = src[(row0 + rr) * 64 + kbase + kk];
        }
        #pragma unroll
        for (int e = 0; e < 8; e++) {
            int idx = e * 256 + tid;
            int kk = idx >> 6, j = idx & 63;
            sBT[j][kk] = W[(kglob + kk) * 64 + j];
        }
        __syncthreads();

        #pragma unroll
        for (int k4 = 0; k4 < 8; k4++) {
            ulonglong2 a[4], b[4];
            #pragma unroll
            for (int i = 0; i < 4; i++)
                a[i] = *(const ulonglong2*)&sA[ty * 4 + i][k4 * 4];
            #pragma unroll
            for (int j = 0; j < 4; j++)
                b[j] = *(const ulonglong2*)&sBT[tx * 4 + j][k4 * 4];
            #pragma unroll
            for (int i = 0; i < 4; i++)
                #pragma unroll
                for (int j = 0; j < 4; j++) {
                    c[i][j] = f2fma(a[i].x, b[j].x, c[i][j]);
                    c[i][j] = f2fma(a[i].y, b[j].y, c[i][j]);
                }
        }
        __syncthreads();
    }

    // horizontal reduce lanes + bias + relu
    float cf[4][4];
    #pragma unroll
    for (int i = 0; i < 4; i++)
        #pragma unroll
        for (int j = 0; j < 4; j++) {
            float lo, hi; upk(c[i][j], lo, hi);
            cf[i][j] = fmaxf(lo + hi + bv[tx * 4 + j], 0.0f);
        }

    if (mat == 0) {
        // q: [h][bt][n][d] row-major; thread's 4 cols lie inside one head
        const int w  = tx * 4;
        const int h  = w >> 3;
        const int dd = w & 7;
        #pragma unroll
        for (int i = 0; i < 4; i++) {
            int n = n0b + ty * 4 + i;
            float4 o = make_float4(cf[i][0], cf[i][1], cf[i][2], cf[i][3]);
            *(float4*)&gout[(((h * NBT) + bt) * NSEQ + n) * HD + dd] = o;
        }
    } else {
        // k/v: transposed [h][bt][d][n]; 4 consecutive tokens -> float4 over n
        const int n0 = n0b + ty * 4;
        #pragma unroll
        for (int j = 0; j < 4; j++) {
            int col = tx * 4 + j;
            int h = col >> 3, dd = col & 7;
            float4 o = make_float4(cf[0][j], cf[1][j], cf[2][j], cf[3][j]);
            *(float4*)&gout[(((h * NBT) + bt) * HD + dd) * NSEQ + n0] = o;
        }
    }
}

// ---------------------------------------------------------------------------
// Kernel 2: attention per (bt, head). K,V transposed in smem ([d][512]);
// everything j-packed in f32x2 lanes. 512 threads, 1 query each.
// ---------------------------------------------------------------------------
__global__ __launch_bounds__(512) void attn_kernel()
{
    __shared__ __align__(16) float skT[HD * NSEQ];
    __shared__ __align__(16) float svT[HD * NSEQ];

    const int bt = blockIdx.x;
    const int h  = blockIdx.y;
    const int tid = threadIdx.x;
    const int base = (h * NBT + bt) * NSEQ * HD;

    // k/v already transposed in gmem -> straight copy
    {
        const float4* gk4 = (const float4*)(g_k + base);
        const float4* gv4 = (const float4*)(g_v + base);
        float4* sk4 = (float4*)skT;
        float4* sv4 = (float4*)svT;
        sk4[tid] = gk4[tid];
        sk4[tid + 512] = gk4[tid + 512];
        sv4[tid] = gv4[tid];
        sv4[tid + 512] = gv4[tid + 512];
    }

    // q: duplicated pairs, pre-scaled
    const float scale = 0.35355339059327373f;   // 1/sqrt(8)
    u64 qp[8];
    {
        const float4* gq4 = (const float4*)(g_q + base);
        float4 a = gq4[tid * 2], b = gq4[tid * 2 + 1];
        qp[0] = pk2(a.x * scale, a.x * scale);
        qp[1] = pk2(a.y * scale, a.y * scale);
        qp[2] = pk2(a.z * scale, a.z * scale);
        qp[3] = pk2(a.w * scale, a.w * scale);
        qp[4] = pk2(b.x * scale, b.x * scale);
        qp[5] = pk2(b.y * scale, b.y * scale);
        qp[6] = pk2(b.z * scale, b.z * scale);
        qp[7] = pk2(b.w * scale, b.w * scale);
    }
    __syncthreads();

    u64 acc[8];
    #pragma unroll
    for (int d = 0; d < 8; d++) acc[d] = 0ull;
    u64 lp = 0ull;

    #pragma unroll 2
    for (int j = 0; j < NSEQ; j += 4) {
        // scores for 4 keys: two packed pairs
        u64 s0 = 0ull, s1 = 0ull;
        ulonglong2 vv[8];
        #pragma unroll
        for (int d = 0; d < 8; d++) {
            ulonglong2 kk = *(const ulonglong2*)(skT + (d << 9) + j);
            vv[d] = *(const ulonglong2*)(svT + (d << 9) + j);
            s0 = f2fma(qp[d], kk.x, s0);
            s1 = f2fma(qp[d], kk.y, s1);
        }

        u64 p0 = fexp2pk(s0);
        u64 p1 = fexp2pk(s1);
        lp = f2add(lp, p0);
        lp = f2add(lp, p1);

        #pragma unroll
        for (int d = 0; d < 8; d++) {
            acc[d] = f2fma(p0, vv[d].x, acc[d]);
            acc[d] = f2fma(p1, vv[d].y, acc[d]);
        }
    }

    float la, lb; upk(lp, la, lb);
    float rcp = 1.0f / (la + lb);

    const int tok = bt * NSEQ + tid;
    float o[8];
    #pragma unroll
    for (int d = 0; d < 8; d++) {
        float a, b; upk(acc[d], a, b);
        o[d] = (a + b) * rcp;
    }
    float* op = &g_att[tok * DMODEL + h * HD];
    *(float4*)op       = make_float4(o[0], o[1], o[2], o[3]);
    *(float4*)(op + 4) = make_float4(o[4], o[5], o[6], o[7]);
}

// ---------------------------------------------------------------------------
// Kernel 3: out = relu(att @ W10 + b10) @ W11 + b11, i-packed f32x2.
// Weights transposed in smem; one row per thread. grid 384 x 128.
// ---------------------------------------------------------------------------
__global__ __launch_bounds__(128) void proj_kernel(
    const float* __restrict__ W10, const float* __restrict__ b10,
    const float* __restrict__ W11, const float* __restrict__ b11,
    float* __restrict__ out)
{
    __shared__ __align__(16) float sW10T[64][68];
    __shared__ __align__(16) float sW11T[64][68];
    __shared__ float sb10[64], sb11[64];

    const int tid = threadIdx.x;
    for (int e = tid; e < 4096; e += 128) {
        int i = e >> 6, j = e & 63;
        sW10T[j][i] = W10[e];
        sW11T[j][i] = W11[e];
    }
    if (tid < 64) { sb10[tid] = b10[tid]; sb11[tid] = b11[tid]; }
    __syncthreads();

    const int row = blockIdx.x * 128 + tid;
    ulonglong2 xr[16];
    {
        const ulonglong2* xg = (const ulonglong2*)(g_att + row * DMODEL);
        #pragma unroll
        for (int q = 0; q < 16; q++) xr[q] = xg[q];
    }

    float hbuf[64];
    #pragma unroll 4
    for (int j = 0; j < 64; j++) {
        u64 hp = 0ull;
        const ulonglong2* w = (const ulonglong2*)&sW10T[j][0];
        #pragma unroll
        for (int q = 0; q < 16; q++) {
            ulonglong2 wv = w[q];
            hp = f2fma(xr[q].x, wv.x, hp);
            hp = f2fma(xr[q].y, wv.y, hp);
        }
        float a, b; upk(hp, a, b);
        hbuf[j] = fmaxf(a + b + sb10[j], 0.0f);
    }

    u64 hp2[32];
    #pragma unroll
    for (int t = 0; t < 32; t++) hp2[t] = pk2(hbuf[2 * t], hbuf[2 * t + 1]);

    float* orow = out + row * DMODEL;
    #pragma unroll 1
    for (int jq = 0; jq < 16; jq++) {
        float ob[4];
        #pragma unroll
        for (int jj = 0; jj < 4; jj++) {
            int j = jq * 4 + jj;
            u64 yp = 0ull;
            const ulonglong2* w = (const ulonglong2*)&sW11T[j][0];
            #pragma unroll
            for (int q = 0; q < 16; q++) {
                ulonglong2 wv = w[q];
                yp = f2fma(hp2[2 * q], wv.x, yp);
                yp = f2fma(hp2[2 * q + 1], wv.y, yp);
            }
            float a, b; upk(yp, a, b);
            ob[jj] = a + b + sb11[j];
        }
        *(float4*)&orow[jq * 4] = make_float4(ob[0], ob[1], ob[2], ob[3]);
    }
}

// ---------------------------------------------------------------------------
extern "C" void kernel_launch(void* const* d_in, const int* in_sizes, int n_in,
                              void* d_out, int out_size)
{
    const float* X   = (const float*)d_in[0];
    const float* STE = (const float*)d_in[1];
    const float* W7  = (const float*)d_in[2];
    const float* b7  = (const float*)d_in[3];
    const float* W8  = (const float*)d_in[4];
    const float* b8  = (const float*)d_in[5];
    const float* W9  = (const float*)d_in[6];
    const float* b9  = (const float*)d_in[7];
    const float* W10 = (const float*)d_in[8];
    const float* b10 = (const float*)d_in[9];
    const float* W11 = (const float*)d_in[10];
    const float* b11 = (const float*)d_in[11];
    float* out = (float*)d_out;

    qkv_kernel<<<dim3(TOKENS / 64, 3), 256>>>(X, STE, W7, b7, W8, b8, W9, b9);
    attn_kernel<<<dim3(NBT, KH), 512>>>();
    proj_kernel<<<TOKENS / 128, 128>>>(W10, b10, W11, b11, out);
}

// round 3
// speedup vs baseline: 1.2712x; 1.2712x over previous
#include <cuda_runtime.h>

// Problem constants
#define NBT   96      // B*T
#define NSEQ  512     // N
#define DMODEL 64
#define KH    8
#define HD    8
#define TOKENS (NBT * NSEQ)   // 49152

typedef unsigned long long u64;

// Scratch: q row-major [h][bt][n][d]; k,v TRANSPOSED [h][bt][d][n]; att [tok][64]
__device__ float g_q[KH * NBT * NSEQ * HD];
__device__ float g_k[KH * NBT * NSEQ * HD];
__device__ float g_v[KH * NBT * NSEQ * HD];
__device__ float g_att[TOKENS * DMODEL];

// ---------------- f32x2 packed-pair primitives (FFMA2 path) ----------------
__device__ __forceinline__ u64 pk2(float a, float b) {
    u64 r; asm("mov.b64 %0, {%1,%2};" : "=l"(r) : "f"(a), "f"(b)); return r;
}
__device__ __forceinline__ void upk(u64 v, float& a, float& b) {
    asm("mov.b64 {%0,%1}, %2;" : "=f"(a), "=f"(b) : "l"(v));
}
__device__ __forceinline__ u64 f2fma(u64 a, u64 b, u64 c) {
    u64 d; asm("fma.rn.f32x2 %0, %1, %2, %3;" : "=l"(d) : "l"(a), "l"(b), "l"(c)); return d;
}
__device__ __forceinline__ u64 f2add(u64 a, u64 b) {
    u64 d; asm("add.rn.f32x2 %0, %1, %2;" : "=l"(d) : "l"(a), "l"(b)); return d;
}

// Packed exp2 of two fp32 lanes, input in log2 domain, x >= 0.
// 2^x = 2^n * 2^g, n = rint(x), |g| <= 0.5. 7 fma-pipe ops for TWO exps;
// the 2^n scaling is exponent-bit addition on the ALU pipe (exact, n in [0,512)).
__device__ __forceinline__ u64 exp2pk(u64 x) {
    const u64 MAGIC  = pk2(12582912.0f, 12582912.0f);     // 1.5 * 2^23
    const u64 NMAGIC = pk2(-12582912.0f, -12582912.0f);
    const u64 NEG1   = pk2(-1.0f, -1.0f);
    const u64 C4     = pk2(9.6181291e-3f, 9.6181291e-3f);   // ln2^4/24
    const u64 C3     = pk2(5.5504109e-2f, 5.5504109e-2f);   // ln2^3/6
    const u64 C2     = pk2(2.4022651e-1f, 2.4022651e-1f);   // ln2^2/2
    const u64 C1     = pk2(6.9314718e-1f, 6.9314718e-1f);   // ln2
    const u64 ONE    = pk2(1.0f, 1.0f);

    u64 t = f2add(x, MAGIC);          // low mantissa bits of t hold n
    float ta, tb; upk(t, ta, tb);
    u64 r = f2add(t, NMAGIC);         // r = rint(x)
    u64 g = f2fma(r, NEG1, x);        // g = x - r, |g| <= 0.5
    u64 p = f2fma(C4, g, C3);
    p = f2fma(p, g, C2);
    p = f2fma(p, g, C1);
    p = f2fma(p, g, ONE);
    p = f2fma(p, g, ONE);             // wait -- see note below
    return p;                          // placeholder (replaced by bit-scale variant)
}

// Real version used: returns 2^x with exponent-bit scaling.
__device__ __forceinline__ u64 exp2pk_bits(u64 x) {
    const u64 MAGIC  = pk2(12582912.0f, 12582912.0f);
    const u64 NMAGIC = pk2(-12582912.0f, -12582912.0f);
    const u64 NEG1   = pk2(-1.0f, -1.0f);
    const u64 C4     = pk2(9.6181291e-3f, 9.6181291e-3f);
    const u64 C3     = pk2(5.5504109e-2f, 5.5504109e-2f);
    const u64 C2     = pk2(2.4022651e-1f, 2.4022651e-1f);
    const u64 C1     = pk2(6.9314718e-1f, 6.9314718e-1f);
    const u64 ONE    = pk2(1.0f, 1.0f);

    u64 t = f2add(x, MAGIC);
    float ta, tb; upk(t, ta, tb);
    u64 r = f2add(t, NMAGIC);
    u64 g = f2fma(r, NEG1, x);          // g = x - rint(x)
    u64 p = f2fma(C4, g, C3);
    p = f2fma(p, g, C2);
    p = f2fma(p, g, C1);
    p = f2fma(p, g, ONE);               // p = 2^g  (1 + g*P(g) form folded)
    // scale by 2^n exactly: add n<<23 to exponent bits (ALU pipe).
    // bits(12582912+n)<<23 == n<<23 (mod 2^32) for 0 <= n < 512.
    float pa, pb; upk(p, pa, pb);
    unsigned ia = __float_as_uint(pa) + (__float_as_uint(ta) << 23);
    unsigned ib = __float_as_uint(pb) + (__float_as_uint(tb) << 23);
    return pk2(__uint_as_float(ia), __uint_as_float(ib));
}

// ---------------------------------------------------------------------------
// Kernel 1: fused QKV projection, output-column-packed f32x2.
// A tile stored as duplicated (a,a) u64 pairs -> FFMA2 broadcast operand free.
// B tile in proven conflict-free [k][64] layout.
// grid (768, 3), 256 threads, 64x64 tile, 4 rows x 2 col-pairs per thread.
// ---------------------------------------------------------------------------
__global__ __launch_bounds__(256) void qkv_kernel(
    const float* __restrict__ X, const float* __restrict__ STE,
    const float* __restrict__ W7, const float* __restrict__ b7,
    const float* __restrict__ W8, const float* __restrict__ b8,
    const float* __restrict__ W9, const float* __restrict__ b9)
{
    __shared__ __align__(16) u64   sA2[64][34];   // [row][k] duplicated pairs, pad->34
    __shared__ __align__(16) float sB[32][64];    // [k][col]

    const int mat = blockIdx.y;
    const float* W  = (mat == 0) ? W7 : (mat == 1) ? W8 : W9;
    const float* bv = (mat == 0) ? b7 : (mat == 1) ? b8 : b9;
    float* gout     = (mat == 0) ? g_q : (mat == 1) ? g_k : g_v;

    const int row0 = blockIdx.x * 64;
    const int bt   = row0 >> 9;
    const int n0b  = row0 & 511;
    const int tid  = threadIdx.x;
    const int tx   = tid & 15;     // 4 cols each (2 packed pairs)
    const int ty   = tid >> 4;     // 4 rows each

    u64 c2[4][2];
    #pragma unroll
    for (int i = 0; i < 4; i++) { c2[i][0] = 0ull; c2[i][1] = 0ull; }

    #pragma unroll 1
    for (int kc = 0; kc < 4; kc++) {
        const float* src = (kc < 2) ? X : STE;
        const int kbase = (kc & 1) * 32;
        const int kglob = kc * 32;

        // A tile: 64 rows x 32 k, stored as (v,v) u64
        #pragma unroll
        for (int e = 0; e < 8; e++) {
            int idx = e * 256 + tid;
            int rr = idx >> 5, kk = idx & 31;
            float v = src[(row0 + rr) * 64 + kbase + kk];
            sA2[rr][kk] = pk2(v, v);
        }
        // B tile: 32 k x 64 cols (coalesced, conflict-free reads later)
        #pragma unroll
        for (int e = 0; e < 8; e++) {
            int idx = e * 256 + tid;
            int kk = idx >> 6, j = idx & 63;
            sB[kk][j] = W[(kglob + kk) * 64 + j];
        }
        __syncthreads();

        #pragma unroll
        for (int k2 = 0; k2 < 16; k2++) {
            ulonglong2 a0 = *(const ulonglong2*)&sA2[ty * 4 + 0][k2 * 2];
            ulonglong2 a1 = *(const ulonglong2*)&sA2[ty * 4 + 1][k2 * 2];
            ulonglong2 a2 = *(const ulonglong2*)&sA2[ty * 4 + 2][k2 * 2];
            ulonglong2 a3 = *(const ulonglong2*)&sA2[ty * 4 + 3][k2 * 2];
            ulonglong2 b0 = *(const ulonglong2*)&sB[k2 * 2][tx * 4];
            ulonglong2 b1 = *(const ulonglong2*)&sB[k2 * 2 + 1][tx * 4];

            c2[0][0] = f2fma(a0.x, b0.x, c2[0][0]);
            c2[0][1] = f2fma(a0.x, b0.y, c2[0][1]);
            c2[1][0] = f2fma(a1.x, b0.x, c2[1][0]);
            c2[1][1] = f2fma(a1.x, b0.y, c2[1][1]);
            c2[2][0] = f2fma(a2.x, b0.x, c2[2][0]);
            c2[2][1] = f2fma(a2.x, b0.y, c2[2][1]);
            c2[3][0] = f2fma(a3.x, b0.x, c2[3][0]);
            c2[3][1] = f2fma(a3.x, b0.y, c2[3][1]);

            c2[0][0] = f2fma(a0.y, b1.x, c2[0][0]);
            c2[0][1] = f2fma(a0.y, b1.y, c2[0][1]);
            c2[1][0] = f2fma(a1.y, b1.x, c2[1][0]);
            c2[1][1] = f2fma(a1.y, b1.y, c2[1][1]);
            c2[2][0] = f2fma(a2.y, b1.x, c2[2][0]);
            c2[2][1] = f2fma(a2.y, b1.y, c2[2][1]);
            c2[3][0] = f2fma(a3.y, b1.x, c2[3][0]);
            c2[3][1] = f2fma(a3.y, b1.y, c2[3][1]);
        }
        __syncthreads();
    }

    // unpack + bias + relu (lanes are complete dot products, no reduce)
    float cf[4][4];
    #pragma unroll
    for (int i = 0; i < 4; i++) {
        upk(c2[i][0], cf[i][0], cf[i][1]);
        upk(c2[i][1], cf[i][2], cf[i][3]);
        #pragma unroll
        for (int j = 0; j < 4; j++)
            cf[i][j] = fmaxf(cf[i][j] + bv[tx * 4 + j], 0.0f);
    }

    if (mat == 0) {
        // q: [h][bt][n][d] row-major; thread's 4 cols lie inside one head
        const int w  = tx * 4;
        const int h  = w >> 3;
        const int dd = w & 7;
        #pragma unroll
        for (int i = 0; i < 4; i++) {
            int n = n0b + ty * 4 + i;
            float4 o = make_float4(cf[i][0], cf[i][1], cf[i][2], cf[i][3]);
            *(float4*)&gout[(((h * NBT) + bt) * NSEQ + n) * HD + dd] = o;
        }
    } else {
        // k/v: transposed [h][bt][d][n]
        const int n0 = n0b + ty * 4;
        #pragma unroll
        for (int j = 0; j < 4; j++) {
            int col = tx * 4 + j;
            int h = col >> 3, dd = col & 7;
            float4 o = make_float4(cf[0][j], cf[1][j], cf[2][j], cf[3][j]);
            *(float4*)&gout[(((h * NBT) + bt) * HD + dd) * NSEQ + n0] = o;
        }
    }
}

// ---------------------------------------------------------------------------
// Kernel 2: attention per (bt, head). K,V transposed in smem ([d][512]);
// j-packed f32x2; scores computed directly in log2 domain (q pre-scaled by
// log2e/sqrt(8)); exp via exp2pk_bits (7 fma ops / pair).
// grid (96, 8), 512 threads, 1 query each.
// ---------------------------------------------------------------------------
__global__ __launch_bounds__(512) void attn_kernel()
{
    __shared__ __align__(16) float skT[HD * NSEQ];
    __shared__ __align__(16) float svT[HD * NSEQ];

    const int bt = blockIdx.x;
    const int h  = blockIdx.y;
    const int tid = threadIdx.x;
    const int base = (h * NBT + bt) * NSEQ * HD;

    {
        const float4* gk4 = (const float4*)(g_k + base);
        const float4* gv4 = (const float4*)(g_v + base);
        float4* sk4 = (float4*)skT;
        float4* sv4 = (float4*)svT;
        sk4[tid] = gk4[tid];
        sk4[tid + 512] = gk4[tid + 512];
        sv4[tid] = gv4[tid];
        sv4[tid + 512] = gv4[tid + 512];
    }

    // q duplicated pairs, pre-scaled by log2e / sqrt(8)
    const float scale = 0.35355339059327373f * 1.4426950408889634f;
    u64 qp[8];
    {
        const float4* gq4 = (const float4*)(g_q + base);
        float4 a = gq4[tid * 2], b = gq4[tid * 2 + 1];
        qp[0] = pk2(a.x * scale, a.x * scale);
        qp[1] = pk2(a.y * scale, a.y * scale);
        qp[2] = pk2(a.z * scale, a.z * scale);
        qp[3] = pk2(a.w * scale, a.w * scale);
        qp[4] = pk2(b.x * scale, b.x * scale);
        qp[5] = pk2(b.y * scale, b.y * scale);
        qp[6] = pk2(b.z * scale, b.z * scale);
        qp[7] = pk2(b.w * scale, b.w * scale);
    }
    __syncthreads();

    u64 acc[8];
    #pragma unroll
    for (int d = 0; d < 8; d++) acc[d] = 0ull;
    u64 lp = 0ull;

    #pragma unroll 2
    for (int j = 0; j < NSEQ; j += 4) {
        u64 s0 = 0ull, s1 = 0ull;
        ulonglong2 vv[8];
        #pragma unroll
        for (int d = 0; d < 8; d++) {
            ulonglong2 kk = *(const ulonglong2*)(skT + (d << 9) + j);
            vv[d] = *(const ulonglong2*)(svT + (d << 9) + j);
            s0 = f2fma(qp[d], kk.x, s0);
            s1 = f2fma(qp[d], kk.y, s1);
        }

        u64 p0 = exp2pk_bits(s0);
        u64 p1 = exp2pk_bits(s1);
        lp = f2add(lp, p0);
        lp = f2add(lp, p1);

        #pragma unroll
        for (int d = 0; d < 8; d++) {
            acc[d] = f2fma(p0, vv[d].x, acc[d]);
            acc[d] = f2fma(p1, vv[d].y, acc[d]);
        }
    }

    float la, lb; upk(lp, la, lb);
    float rcp = 1.0f / (la + lb);

    const int tok = bt * NSEQ + tid;
    float o[8];
    #pragma unroll
    for (int d = 0; d < 8; d++) {
        float a, b; upk(acc[d], a, b);
        o[d] = (a + b) * rcp;
    }
    float* op = &g_att[tok * DMODEL + h * HD];
    *(float4*)op       = make_float4(o[0], o[1], o[2], o[3]);
    *(float4*)(op + 4) = make_float4(o[4], o[5], o[6], o[7]);
}

// ---------------------------------------------------------------------------
// Kernel 3: out = relu(att @ W10 + b10) @ W11 + b11, i-packed f32x2.
// Weights transposed in smem (broadcast reads); one row per thread.
// ---------------------------------------------------------------------------
__global__ __launch_bounds__(128) void proj_kernel(
    const float* __restrict__ W10, const float* __restrict__ b10,
    const float* __restrict__ W11, const float* __restrict__ b11,
    float* __restrict__ out)
{
    __shared__ __align__(16) float sW10T[64][68];
    __shared__ __align__(16) float sW11T[64][68];
    __shared__ float sb10[64], sb11[64];

    const int tid = threadIdx.x;
    for (int e = tid; e < 4096; e += 128) {
        int i = e >> 6, j = e & 63;
        sW10T[j][i] = W10[e];
        sW11T[j][i] = W11[e];
    }
    if (tid < 64) { sb10[tid] = b10[tid]; sb11[tid] = b11[tid]; }
    __syncthreads();

    const int row = blockIdx.x * 128 + tid;
    ulonglong2 xr[16];
    {
        const ulonglong2* xg = (const ulonglong2*)(g_att + row * DMODEL);
        #pragma unroll
        for (int q = 0; q < 16; q++) xr[q] = xg[q];
    }

    float hbuf[64];
    #pragma unroll 4
    for (int j = 0; j < 64; j++) {
        u64 hp = 0ull;
        const ulonglong2* w = (const ulonglong2*)&sW10T[j][0];
        #pragma unroll
        for (int q = 0; q < 16; q++) {
            ulonglong2 wv = w[q];
            hp = f2fma(xr[q].x, wv.x, hp);
            hp = f2fma(xr[q].y, wv.y, hp);
        }
        float a, b; upk(hp, a, b);
        hbuf[j] = fmaxf(a + b + sb10[j], 0.0f);
    }

    u64 hp2[32];
    #pragma unroll
    for (int t = 0; t < 32; t++) hp2[t] = pk2(hbuf[2 * t], hbuf[2 * t + 1]);

    float* orow = out + row * DMODEL;
    #pragma unroll 1
    for (int jq = 0; jq < 16; jq++) {
        float ob[4];
        #pragma unroll
        for (int jj = 0; jj < 4; jj++) {
            int j = jq * 4 + jj;
            u64 yp = 0ull;
            const ulonglong2* w = (const ulonglong2*)&sW11T[j][0];
            #pragma unroll
            for (int q = 0; q < 16; q++) {
                ulonglong2 wv = w[q];
                yp = f2fma(hp2[2 * q], wv.x, yp);
                yp = f2fma(hp2[2 * q + 1], wv.y, yp);
            }
            float a, b; upk(yp, a, b);
            ob[jj] = a + b + sb11[j];
        }
        *(float4*)&orow[jq * 4] = make_float4(ob[0], ob[1], ob[2], ob[3]);
    }
}

// ---------------------------------------------------------------------------
extern "C" void kernel_launch(void* const* d_in, const int* in_sizes, int n_in,
                              void* d_out, int out_size)
{
    const float* X   = (const float*)d_in[0];
    const float* STE = (const float*)d_in[1];
    const float* W7  = (const float*)d_in[2];
    const float* b7  = (const float*)d_in[3];
    const float* W8  = (const float*)d_in[4];
    const float* b8  = (const float*)d_in[5];
    const float* W9  = (const float*)d_in[6];
    const float* b9  = (const float*)d_in[7];
    const float* W10 = (const float*)d_in[8];
    const float* b10 = (const float*)d_in[9];
    const float* W11 = (const float*)d_in[10];
    const float* b11 = (const float*)d_in[11];
    float* out = (float*)d_out;

    qkv_kernel<<<dim3(TOKENS / 64, 3), 256>>>(X, STE, W7, b7, W8, b8, W9, b9);
    attn_kernel<<<dim3(NBT, KH), 512>>>();
    proj_kernel<<<TOKENS / 128, 128>>>(W10, b10, W11, b11, out);
}

// round 4
// speedup vs baseline: 1.3620x; 1.0714x over previous
#include <cuda_runtime.h>

// Problem constants
#define NBT   96      // B*T
#define NSEQ  512     // N
#define DMODEL 64
#define KH    8
#define HD    8
#define TOKENS (NBT * NSEQ)   // 49152

typedef unsigned long long u64;

// Scratch: q row-major [h][bt][n][d]; k,v TRANSPOSED [h][bt][d][n]; att [tok][64]
__device__ float g_q[KH * NBT * NSEQ * HD];
__device__ float g_k[KH * NBT * NSEQ * HD];
__device__ float g_v[KH * NBT * NSEQ * HD];
__device__ float g_att[TOKENS * DMODEL];

// ---------------- f32x2 packed-pair primitives (FFMA2 path) ----------------
__device__ __forceinline__ u64 pk2(float a, float b) {
    u64 r; asm("mov.b64 %0, {%1,%2};" : "=l"(r) : "f"(a), "f"(b)); return r;
}
__device__ __forceinline__ void upk(u64 v, float& a, float& b) {
    asm("mov.b64 {%0,%1}, %2;" : "=f"(a), "=f"(b) : "l"(v));
}
__device__ __forceinline__ u64 f2fma(u64 a, u64 b, u64 c) {
    u64 d; asm("fma.rn.f32x2 %0, %1, %2, %3;" : "=l"(d) : "l"(a), "l"(b), "l"(c)); return d;
}
__device__ __forceinline__ u64 f2add(u64 a, u64 b) {
    u64 d; asm("add.rn.f32x2 %0, %1, %2;" : "=l"(d) : "l"(a), "l"(b)); return d;
}

// Packed 2^x of two fp32 lanes, x >= 0 (log2-domain scores).
// 2^x = 2^n * 2^g, n = rint(x), |g| <= 0.5; 2^n applied via exponent-bit
// addition on the ALU pipe (exact for 0 <= n < 512). ~7 fma ops / 2 exps.
__device__ __forceinline__ u64 exp2pk_bits(u64 x) {
    const u64 MAGIC  = pk2(12582912.0f, 12582912.0f);
    const u64 NMAGIC = pk2(-12582912.0f, -12582912.0f);
    const u64 NEG1   = pk2(-1.0f, -1.0f);
    const u64 C4     = pk2(9.6181291e-3f, 9.6181291e-3f);
    const u64 C3     = pk2(5.5504109e-2f, 5.5504109e-2f);
    const u64 C2     = pk2(2.4022651e-1f, 2.4022651e-1f);
    const u64 C1     = pk2(6.9314718e-1f, 6.9314718e-1f);
    const u64 ONE    = pk2(1.0f, 1.0f);

    u64 t = f2add(x, MAGIC);
    float ta, tb; upk(t, ta, tb);
    u64 r = f2add(t, NMAGIC);
    u64 g = f2fma(r, NEG1, x);          // g = x - rint(x)
    u64 p = f2fma(C4, g, C3);
    p = f2fma(p, g, C2);
    p = f2fma(p, g, C1);
    p = f2fma(p, g, ONE);               // p = 2^g
    float pa, pb; upk(p, pa, pb);
    unsigned ia = __float_as_uint(pa) + (__float_as_uint(ta) << 23);
    unsigned ib = __float_as_uint(pb) + (__float_as_uint(tb) << 23);
    return pk2(__uint_as_float(ia), __uint_as_float(ib));
}

// ---------------------------------------------------------------------------
// Kernel 1: fused QKV projection, col-packed f32x2, high fma:LDS ratio.
// Block tile 128 rows x 64 cols, 256 threads, per-thread 8 rows x 4 cols.
// A read as scalar float2 (broadcast-ish), pairs built on ALU pipe.
// grid (384, 3).
// ---------------------------------------------------------------------------
#define QKV_ASTRIDE 34
__global__ __launch_bounds__(256) void qkv_kernel(
    const float* __restrict__ X, const float* __restrict__ STE,
    const float* __restrict__ W7, const float* __restrict__ b7,
    const float* __restrict__ W8, const float* __restrict__ b8,
    const float* __restrict__ W9, const float* __restrict__ b9)
{
    __shared__ __align__(16) float sA[128 * QKV_ASTRIDE];  // [row][k], stride 34
    __shared__ __align__(16) float sB[32][64];              // [k][col]

    const int mat = blockIdx.y;
    const float* W  = (mat == 0) ? W7 : (mat == 1) ? W8 : W9;
    const float* bv = (mat == 0) ? b7 : (mat == 1) ? b8 : b9;
    float* gout     = (mat == 0) ? g_q : (mat == 1) ? g_k : g_v;

    const int row0 = blockIdx.x * 128;
    const int bt   = row0 >> 9;
    const int n0b  = row0 & 511;
    const int tid  = threadIdx.x;
    const int tx   = tid & 15;     // 4 cols (2 packed pairs)
    const int ty   = tid >> 4;     // 16 groups x 8 rows
    const int r0   = ty * 8;

    u64 c2[8][2];
    #pragma unroll
    for (int i = 0; i < 8; i++) { c2[i][0] = 0ull; c2[i][1] = 0ull; }

    #pragma unroll 1
    for (int kc = 0; kc < 4; kc++) {
        const float* src = (kc < 2) ? X : STE;
        const int kbase = (kc & 1) * 32;
        const int kglob = kc * 32;

        // A tile: 128 rows x 32 k (16 elems/thread, coalesced over k)
        #pragma unroll
        for (int e = 0; e < 16; e++) {
            int idx = e * 256 + tid;
            int rr = idx >> 5, kk = idx & 31;
            sA[rr * QKV_ASTRIDE + kk] = src[(row0 + rr) * 64 + kbase + kk];
        }
        // B tile: 32 k x 64 cols
        #pragma unroll
        for (int e = 0; e < 8; e++) {
            int idx = e * 256 + tid;
            int kk = idx >> 6, j = idx & 63;
            sB[kk][j] = W[(kglob + kk) * 64 + j];
        }
        __syncthreads();

        #pragma unroll
        for (int k2 = 0; k2 < 16; k2++) {
            ulonglong2 b0 = *(const ulonglong2*)&sB[k2 * 2][tx * 4];
            ulonglong2 b1 = *(const ulonglong2*)&sB[k2 * 2 + 1][tx * 4];
            #pragma unroll
            for (int i = 0; i < 8; i++) {
                float2 a = *(const float2*)&sA[(r0 + i) * QKV_ASTRIDE + k2 * 2];
                u64 pa = pk2(a.x, a.x);
                u64 pb = pk2(a.y, a.y);
                c2[i][0] = f2fma(pa, b0.x, c2[i][0]);
                c2[i][1] = f2fma(pa, b0.y, c2[i][1]);
                c2[i][0] = f2fma(pb, b1.x, c2[i][0]);
                c2[i][1] = f2fma(pb, b1.y, c2[i][1]);
            }
        }
        __syncthreads();
    }

    // unpack + bias + relu
    float cf[8][4];
    const float bx = bv[tx * 4 + 0], by = bv[tx * 4 + 1];
    const float bz = bv[tx * 4 + 2], bw = bv[tx * 4 + 3];
    #pragma unroll
    for (int i = 0; i < 8; i++) {
        upk(c2[i][0], cf[i][0], cf[i][1]);
        upk(c2[i][1], cf[i][2], cf[i][3]);
        cf[i][0] = fmaxf(cf[i][0] + bx, 0.0f);
        cf[i][1] = fmaxf(cf[i][1] + by, 0.0f);
        cf[i][2] = fmaxf(cf[i][2] + bz, 0.0f);
        cf[i][3] = fmaxf(cf[i][3] + bw, 0.0f);
    }

    if (mat == 0) {
        // q: [h][bt][n][d]; thread's 4 cols lie inside one head
        const int w  = tx * 4;
        const int h  = w >> 3;
        const int dd = w & 7;
        #pragma unroll
        for (int i = 0; i < 8; i++) {
            int n = n0b + r0 + i;
            float4 o = make_float4(cf[i][0], cf[i][1], cf[i][2], cf[i][3]);
            *(float4*)&gout[(((h * NBT) + bt) * NSEQ + n) * HD + dd] = o;
        }
    } else {
        // k/v transposed [h][bt][d][n]: 8 consecutive tokens -> 2x float4 over n
        const int n0 = n0b + r0;
        #pragma unroll
        for (int j = 0; j < 4; j++) {
            int col = tx * 4 + j;
            int h = col >> 3, dd = col & 7;
            float* dst = &gout[(((h * NBT) + bt) * HD + dd) * NSEQ + n0];
            *(float4*)dst       = make_float4(cf[0][j], cf[1][j], cf[2][j], cf[3][j]);
            *(float4*)(dst + 4) = make_float4(cf[4][j], cf[5][j], cf[6][j], cf[7][j]);
        }
    }
}

// ---------------------------------------------------------------------------
// Kernel 2: attention per (bt, head). K,V transposed in smem ([d][512]);
// j-packed f32x2; log2-domain scores; V loaded AFTER exp (low reg pressure).
// grid (96, 8), 512 threads, 1 query each.
// ---------------------------------------------------------------------------
__global__ __launch_bounds__(512) void attn_kernel()
{
    __shared__ __align__(16) float skT[HD * NSEQ];
    __shared__ __align__(16) float svT[HD * NSEQ];

    const int bt = blockIdx.x;
    const int h  = blockIdx.y;
    const int tid = threadIdx.x;
    const int base = (h * NBT + bt) * NSEQ * HD;

    {
        const float4* gk4 = (const float4*)(g_k + base);
        const float4* gv4 = (const float4*)(g_v + base);
        float4* sk4 = (float4*)skT;
        float4* sv4 = (float4*)svT;
        sk4[tid] = gk4[tid];
        sk4[tid + 512] = gk4[tid + 512];
        sv4[tid] = gv4[tid];
        sv4[tid + 512] = gv4[tid + 512];
    }

    // q duplicated pairs, pre-scaled by log2e / sqrt(8)
    const float scale = 0.35355339059327373f * 1.4426950408889634f;
    u64 qp[8];
    {
        const float4* gq4 = (const float4*)(g_q + base);
        float4 a = gq4[tid * 2], b = gq4[tid * 2 + 1];
        qp[0] = pk2(a.x * scale, a.x * scale);
        qp[1] = pk2(a.y * scale, a.y * scale);
        qp[2] = pk2(a.z * scale, a.z * scale);
        qp[3] = pk2(a.w * scale, a.w * scale);
        qp[4] = pk2(b.x * scale, b.x * scale);
        qp[5] = pk2(b.y * scale, b.y * scale);
        qp[6] = pk2(b.z * scale, b.z * scale);
        qp[7] = pk2(b.w * scale, b.w * scale);
    }
    __syncthreads();

    u64 acc[8];
    #pragma unroll
    for (int d = 0; d < 8; d++) acc[d] = 0ull;
    u64 lp0 = 0ull, lp1 = 0ull;

    #pragma unroll 4
    for (int j = 0; j < NSEQ; j += 4) {
        u64 s0 = 0ull, s1 = 0ull;
        #pragma unroll
        for (int d = 0; d < 8; d++) {
            ulonglong2 kk = *(const ulonglong2*)(skT + (d << 9) + j);
            s0 = f2fma(qp[d], kk.x, s0);
            s1 = f2fma(qp[d], kk.y, s1);
        }

        u64 p0 = exp2pk_bits(s0);
        u64 p1 = exp2pk_bits(s1);
        lp0 = f2add(lp0, p0);
        lp1 = f2add(lp1, p1);

        #pragma unroll
        for (int d = 0; d < 8; d++) {
            ulonglong2 vv = *(const ulonglong2*)(svT + (d << 9) + j);
            acc[d] = f2fma(p0, vv.x, acc[d]);
            acc[d] = f2fma(p1, vv.y, acc[d]);
        }
    }

    u64 lp = f2add(lp0, lp1);
    float la, lb; upk(lp, la, lb);
    float rcp = 1.0f / (la + lb);

    const int tok = bt * NSEQ + tid;
    float o[8];
    #pragma unroll
    for (int d = 0; d < 8; d++) {
        float a, b; upk(acc[d], a, b);
        o[d] = (a + b) * rcp;
    }
    float* op = &g_att[tok * DMODEL + h * HD];
    *(float4*)op       = make_float4(o[0], o[1], o[2], o[3]);
    *(float4*)(op + 4) = make_float4(o[4], o[5], o[6], o[7]);
}

// ---------------------------------------------------------------------------
// Kernel 3: out = relu(att @ W10 + b10) @ W11 + b11, i-packed f32x2.
// ---------------------------------------------------------------------------
__global__ __launch_bounds__(128) void proj_kernel(
    const float* __restrict__ W10, const float* __restrict__ b10,
    const float* __restrict__ W11, const float* __restrict__ b11,
    float* __restrict__ out)
{
    __shared__ __align__(16) float sW10T[64][68];
    __shared__ __align__(16) float sW11T[64][68];
    __shared__ float sb10[64], sb11[64];

    const int tid = threadIdx.x;
    for (int e = tid; e < 4096; e += 128) {
        int i = e >> 6, j = e & 63;
        sW10T[j][i] = W10[e];
        sW11T[j][i] = W11[e];
    }
    if (tid < 64) { sb10[tid] = b10[tid]; sb11[tid] = b11[tid]; }
    __syncthreads();

    const int row = blockIdx.x * 128 + tid;
    ulonglong2 xr[16];
    {
        const ulonglong2* xg = (const ulonglong2*)(g_att + row * DMODEL);
        #pragma unroll
        for (int q = 0; q < 16; q++) xr[q] = xg[q];
    }

    float hbuf[64];
    #pragma unroll 4
    for (int j = 0; j < 64; j++) {
        u64 hp = 0ull;
        const ulonglong2* w = (const ulonglong2*)&sW10T[j][0];
        #pragma unroll
        for (int q = 0; q < 16; q++) {
            ulonglong2 wv = w[q];
            hp = f2fma(xr[q].x, wv.x, hp);
            hp = f2fma(xr[q].y, wv.y, hp);
        }
        float a, b; upk(hp, a, b);
        hbuf[j] = fmaxf(a + b + sb10[j], 0.0f);
    }

    u64 hp2[32];
    #pragma unroll
    for (int t = 0; t < 32; t++) hp2[t] = pk2(hbuf[2 * t], hbuf[2 * t + 1]);

    float* orow = out + row * DMODEL;
    #pragma unroll 1
    for (int jq = 0; jq < 16; jq++) {
        float ob[4];
        #pragma unroll
        for (int jj = 0; jj < 4; jj++) {
            int j = jq * 4 + jj;
            u64 yp = 0ull;
            const ulonglong2* w = (const ulonglong2*)&sW11T[j][0];
            #pragma unroll
            for (int q = 0; q < 16; q++) {
                ulonglong2 wv = w[q];
                yp = f2fma(hp2[2 * q], wv.x, yp);
                yp = f2fma(hp2[2 * q + 1], wv.y, yp);
            }
            float a, b; upk(yp, a, b);
            ob[jj] = a + b + sb11[j];
        }
        *(float4*)&orow[jq * 4] = make_float4(ob[0], ob[1], ob[2], ob[3]);
    }
}

// ---------------------------------------------------------------------------
extern "C" void kernel_launch(void* const* d_in, const int* in_sizes, int n_in,
                              void* d_out, int out_size)
{
    const float* X   = (const float*)d_in[0];
    const float* STE = (const float*)d_in[1];
    const float* W7  = (const float*)d_in[2];
    const float* b7  = (const float*)d_in[3];
    const float* W8  = (const float*)d_in[4];
    const float* b8  = (const float*)d_in[5];
    const float* W9  = (const float*)d_in[6];
    const float* b9  = (const float*)d_in[7];
    const float* W10 = (const float*)d_in[8];
    const float* b10 = (const float*)d_in[9];
    const float* W11 = (const float*)d_in[10];
    const float* b11 = (const float*)d_in[11];
    float* out = (float*)d_out;

    qkv_kernel<<<dim3(TOKENS / 128, 3), 256>>>(X, STE, W7, b7, W8, b8, W9, b9);
    attn_kernel<<<dim3(NBT, KH), 512>>>();
    proj_kernel<<<TOKENS / 128, 128>>>(W10, b10, W11, b11, out);
}

// round 5
// speedup vs baseline: 1.7618x; 1.2935x over previous
#include <cuda_runtime.h>

// Problem constants
#define NBT   96      // B*T
#define NSEQ  512     // N
#define DMODEL 64
#define KH    8
#define HD    8
#define TOKENS (NBT * NSEQ)   // 49152

typedef unsigned long long u64;
typedef unsigned int u32;

// Scratch: q,k row-major [h][bt][n][d]; v TRANSPOSED [h][bt][d][n]; att [tok][64]
__device__ float g_q[KH * NBT * NSEQ * HD];
__device__ float g_k[KH * NBT * NSEQ * HD];
__device__ float g_v[KH * NBT * NSEQ * HD];
__device__ float g_att[TOKENS * DMODEL];

// ---------------- f32x2 packed-pair primitives ----------------
__device__ __forceinline__ u64 pk2(float a, float b) {
    u64 r; asm("mov.b64 %0, {%1,%2};" : "=l"(r) : "f"(a), "f"(b)); return r;
}
__device__ __forceinline__ void upk(u64 v, float& a, float& b) {
    asm("mov.b64 {%0,%1}, %2;" : "=f"(a), "=f"(b) : "l"(v));
}
__device__ __forceinline__ u64 f2fma(u64 a, u64 b, u64 c) {
    u64 d; asm("fma.rn.f32x2 %0, %1, %2, %3;" : "=l"(d) : "l"(a), "l"(b), "l"(c)); return d;
}
__device__ __forceinline__ u64 f2add(u64 a, u64 b) {
    u64 d; asm("add.rn.f32x2 %0, %1, %2;" : "=l"(d) : "l"(a), "l"(b)); return d;
}

// Packed 2^x of two fp32 lanes, x >= 0. 2^n applied via exponent-bit add.
__device__ __forceinline__ u64 exp2pk_bits(u64 x) {
    const u64 MAGIC  = pk2(12582912.0f, 12582912.0f);
    const u64 NMAGIC = pk2(-12582912.0f, -12582912.0f);
    const u64 NEG1   = pk2(-1.0f, -1.0f);
    const u64 C4     = pk2(9.6181291e-3f, 9.6181291e-3f);
    const u64 C3     = pk2(5.5504109e-2f, 5.5504109e-2f);
    const u64 C2     = pk2(2.4022651e-1f, 2.4022651e-1f);
    const u64 C1     = pk2(6.9314718e-1f, 6.9314718e-1f);
    const u64 ONE    = pk2(1.0f, 1.0f);

    u64 t = f2add(x, MAGIC);
    float ta, tb; upk(t, ta, tb);
    u64 r = f2add(t, NMAGIC);
    u64 g = f2fma(r, NEG1, x);          // g = x - rint(x)
    u64 p = f2fma(C4, g, C3);
    p = f2fma(p, g, C2);
    p = f2fma(p, g, C1);
    p = f2fma(p, g, ONE);               // p = 2^g
    float pa, pb; upk(p, pa, pb);
    u32 ia = __float_as_uint(pa) + (__float_as_uint(ta) << 23);
    u32 ib = __float_as_uint(pb) + (__float_as_uint(tb) << 23);
    return pk2(__uint_as_float(ia), __uint_as_float(ib));
}

// ---------------- bf16 split helpers ----------------
// pack {lo16 = bf16(x0), hi16 = bf16(x1)}  (low half = lower k/col index)
__device__ __forceinline__ u32 cvt_bf2(float x1, float x0) {
    u32 r; asm("cvt.rn.bf16x2.f32 %0, %1, %2;" : "=r"(r) : "f"(x1), "f"(x0)); return r;
}
__device__ __forceinline__ float bflo(u32 p) { return __uint_as_float(p << 16); }
__device__ __forceinline__ float bfhi(u32 p) { return __uint_as_float(p & 0xffff0000u); }
// split pair (x0,x1) into hi bf16x2 + lo bf16x2 (residuals)
__device__ __forceinline__ void split2(float x0, float x1, u32& hp, u32& lp) {
    hp = cvt_bf2(x1, x0);
    lp = cvt_bf2(x1 - bfhi(hp), x0 - bflo(hp));
}

// m16n8k8 bf16 MMA, f32 accumulate, row.col
__device__ __forceinline__ void mma8(float (&d)[4], u32 a0, u32 a1, u32 b) {
    asm("mma.sync.aligned.m16n8k8.row.col.f32.bf16.bf16.f32 "
        "{%0,%1,%2,%3},{%4,%5},{%6},{%0,%1,%2,%3};"
        : "+f"(d[0]), "+f"(d[1]), "+f"(d[2]), "+f"(d[3])
        : "r"(a0), "r"(a1), "r"(b));
}

// ---------------------------------------------------------------------------
// Kernel 1: fused QKV projection (fp32, col-packed f32x2 — near fp32 roofline).
// q,k written row-major [h][bt][n][d]; v transposed [h][bt][d][n].
// ---------------------------------------------------------------------------
#define QKV_ASTRIDE 34
__global__ __launch_bounds__(256) void qkv_kernel(
    const float* __restrict__ X, const float* __restrict__ STE,
    const float* __restrict__ W7, const float* __restrict__ b7,
    const float* __restrict__ W8, const float* __restrict__ b8,
    const float* __restrict__ W9, const float* __restrict__ b9)
{
    __shared__ __align__(16) float sA[128 * QKV_ASTRIDE];
    __shared__ __align__(16) float sB[32][64];

    const int mat = blockIdx.y;
    const float* W  = (mat == 0) ? W7 : (mat == 1) ? W8 : W9;
    const float* bv = (mat == 0) ? b7 : (mat == 1) ? b8 : b9;
    float* gout     = (mat == 0) ? g_q : (mat == 1) ? g_k : g_v;

    const int row0 = blockIdx.x * 128;
    const int bt   = row0 >> 9;
    const int n0b  = row0 & 511;
    const int tid  = threadIdx.x;
    const int tx   = tid & 15;
    const int ty   = tid >> 4;
    const int r0   = ty * 8;

    u64 c2[8][2];
    #pragma unroll
    for (int i = 0; i < 8; i++) { c2[i][0] = 0ull; c2[i][1] = 0ull; }

    #pragma unroll 1
    for (int kc = 0; kc < 4; kc++) {
        const float* src = (kc < 2) ? X : STE;
        const int kbase = (kc & 1) * 32;
        const int kglob = kc * 32;

        #pragma unroll
        for (int e = 0; e < 16; e++) {
            int idx = e * 256 + tid;
            int rr = idx >> 5, kk = idx & 31;
            sA[rr * QKV_ASTRIDE + kk] = src[(row0 + rr) * 64 + kbase + kk];
        }
        #pragma unroll
        for (int e = 0; e < 8; e++) {
            int idx = e * 256 + tid;
            int kk = idx >> 6, j = idx & 63;
            sB[kk][j] = W[(kglob + kk) * 64 + j];
        }
        __syncthreads();

        #pragma unroll
        for (int k2 = 0; k2 < 16; k2++) {
            ulonglong2 b0 = *(const ulonglong2*)&sB[k2 * 2][tx * 4];
            ulonglong2 b1 = *(const ulonglong2*)&sB[k2 * 2 + 1][tx * 4];
            #pragma unroll
            for (int i = 0; i < 8; i++) {
                float2 a = *(const float2*)&sA[(r0 + i) * QKV_ASTRIDE + k2 * 2];
                u64 pa = pk2(a.x, a.x);
                u64 pb = pk2(a.y, a.y);
                c2[i][0] = f2fma(pa, b0.x, c2[i][0]);
                c2[i][1] = f2fma(pa, b0.y, c2[i][1]);
                c2[i][0] = f2fma(pb, b1.x, c2[i][0]);
                c2[i][1] = f2fma(pb, b1.y, c2[i][1]);
            }
        }
        __syncthreads();
    }

    float cf[8][4];
    const float bx = bv[tx * 4 + 0], by = bv[tx * 4 + 1];
    const float bz = bv[tx * 4 + 2], bw = bv[tx * 4 + 3];
    #pragma unroll
    for (int i = 0; i < 8; i++) {
        upk(c2[i][0], cf[i][0], cf[i][1]);
        upk(c2[i][1], cf[i][2], cf[i][3]);
        cf[i][0] = fmaxf(cf[i][0] + bx, 0.0f);
        cf[i][1] = fmaxf(cf[i][1] + by, 0.0f);
        cf[i][2] = fmaxf(cf[i][2] + bz, 0.0f);
        cf[i][3] = fmaxf(cf[i][3] + bw, 0.0f);
    }

    if (mat != 2) {
        // q,k: row-major [h][bt][n][d]
        const int w  = tx * 4;
        const int h  = w >> 3;
        const int dd = w & 7;
        #pragma unroll
        for (int i = 0; i < 8; i++) {
            int n = n0b + r0 + i;
            float4 o = make_float4(cf[i][0], cf[i][1], cf[i][2], cf[i][3]);
            *(float4*)&gout[(((h * NBT) + bt) * NSEQ + n) * HD + dd] = o;
        }
    } else {
        // v: transposed [h][bt][d][n]
        const int n0 = n0b + r0;
        #pragma unroll
        for (int j = 0; j < 4; j++) {
            int col = tx * 4 + j;
            int h = col >> 3, dd = col & 7;
            float* dst = &gout[(((h * NBT) + bt) * HD + dd) * NSEQ + n0];
            *(float4*)dst       = make_float4(cf[0][j], cf[1][j], cf[2][j], cf[3][j]);
            *(float4*)(dst + 4) = make_float4(cf[4][j], cf[5][j], cf[6][j], cf[7][j]);
        }
    }
}

// ---------------------------------------------------------------------------
// Kernel 2: attention per (bt, head) on tensor cores (m16n8k8 bf16, 3-term
// split). 256 threads = 8 warps; warp w owns query rows [64w, 64w+64).
// Single-pass softmax (scores >= 0); exp2 on fma pipe; S C-frag == P A-frag.
// ---------------------------------------------------------------------------
__global__ __launch_bounds__(256) void attn_kernel()
{
    __shared__ __align__(16) u32 skh[NSEQ * 4];       // K bf16-hi pairs [j][c]
    __shared__ __align__(16) u32 skl[NSEQ * 4];       // K bf16-lo pairs
    __shared__ __align__(16) u32 svh[(NSEQ / 2) * 8]; // V hi pairs [j2][d]
    __shared__ __align__(16) u32 svl[(NSEQ / 2) * 8];

    const int bt   = blockIdx.x;
    const int h    = blockIdx.y;
    const int tid  = threadIdx.x;
    const int lane = tid & 31;
    const int warp = tid >> 5;
    const int base = (h * NBT + bt) * NSEQ * HD;

    // ---- stage K (row-major [j][d] in gmem) -> bf16 hi/lo pair layout ----
    #pragma unroll
    for (int rr = 0; rr < 2; rr++) {
        int r = tid + rr * 256;
        const float4* kp = (const float4*)(g_k + base + r * 8);
        float4 f0 = kp[0], f1 = kp[1];
        u32 h0, l0, h1, l1, h2, l2, h3, l3;
        split2(f0.x, f0.y, h0, l0);
        split2(f0.z, f0.w, h1, l1);
        split2(f1.x, f1.y, h2, l2);
        split2(f1.z, f1.w, h3, l3);
        *(uint4*)&skh[r * 4] = make_uint4(h0, h1, h2, h3);
        *(uint4*)&skl[r * 4] = make_uint4(l0, l1, l2, l3);
    }

    // ---- stage V (transposed [d][j] in gmem) -> pairs over j at fixed d ----
    {
        int dd = tid >> 5;           // 0..7
        int jb = tid & 31;
        const float* vrow = g_v + base + dd * NSEQ;
        #pragma unroll
        for (int it = 0; it < 8; it++) {
            int j2 = jb + it * 32;
            float2 f = *(const float2*)(vrow + 2 * j2);
            u32 hp, lp;
            split2(f.x, f.y, hp, lp);
            svh[j2 * 8 + dd] = hp;
            svl[j2 * 8 + dd] = lp;
        }
    }

    // ---- Q A-fragments (pre-scaled to log2 domain), hi/lo split ----
    const float qscale = 0.35355339059327373f * 1.4426950408889634f;
    u32 qh[4][2], ql[4][2];
    const int m0 = warp * 64;
    {
        const float* qb = g_q + base;
        #pragma unroll
        for (int mt = 0; mt < 4; mt++) {
            int r = m0 + mt * 16 + (lane >> 2);
            float2 f0 = *(const float2*)(qb + r * 8 + (lane & 3) * 2);
            float2 f1 = *(const float2*)(qb + (r + 8) * 8 + (lane & 3) * 2);
            split2(f0.x * qscale, f0.y * qscale, qh[mt][0], ql[mt][0]);
            split2(f1.x * qscale, f1.y * qscale, qh[mt][1], ql[mt][1]);
        }
    }
    __syncthreads();

    float o[4][4];
    #pragma unroll
    for (int mt = 0; mt < 4; mt++)
        #pragma unroll
        for (int e = 0; e < 4; e++) o[mt][e] = 0.0f;
    u64 lA[4], lB[4];
    #pragma unroll
    for (int mt = 0; mt < 4; mt++) { lA[mt] = 0ull; lB[mt] = 0ull; }

    const int vb_idx = (lane & 3) * 8 + (lane >> 2);

    #pragma unroll 1
    for (int j0 = 0; j0 < NSEQ; j0 += 8) {
        u32 bkh = skh[j0 * 4 + lane];
        u32 bkl = skl[j0 * 4 + lane];
        u32 bvh = svh[(j0 >> 1) * 8 + vb_idx];
        u32 bvl = svl[(j0 >> 1) * 8 + vb_idx];

        #pragma unroll
        for (int mt = 0; mt < 4; mt++) {
            float s[4] = {0.0f, 0.0f, 0.0f, 0.0f};
            mma8(s, qh[mt][0], qh[mt][1], bkh);
            mma8(s, qh[mt][0], qh[mt][1], bkl);
            mma8(s, ql[mt][0], ql[mt][1], bkh);

            u64 p01 = exp2pk_bits(pk2(s[0], s[1]));
            u64 p23 = exp2pk_bits(pk2(s[2], s[3]));
            lA[mt] = f2add(lA[mt], p01);
            lB[mt] = f2add(lB[mt], p23);

            float p0, p1, p2, p3;
            upk(p01, p0, p1);
            upk(p23, p2, p3);
            u32 pah, pal, pbh, pbl;
            split2(p0, p1, pah, pal);
            split2(p2, p3, pbh, pbl);

            mma8(o[mt], pah, pbh, bvh);
            mma8(o[mt], pah, pbh, bvl);
            mma8(o[mt], pal, pbl, bvh);
        }
    }

    // ---- normalize and write ----
    #pragma unroll
    for (int mt = 0; mt < 4; mt++) {
        float a, b;
        upk(lA[mt], a, b);
        float l0 = a + b;
        upk(lB[mt], a, b);
        float l1 = a + b;
        l0 += __shfl_xor_sync(0xffffffffu, l0, 1);
        l0 += __shfl_xor_sync(0xffffffffu, l0, 2);
        l1 += __shfl_xor_sync(0xffffffffu, l1, 1);
        l1 += __shfl_xor_sync(0xffffffffu, l1, 2);
        float r0 = __fdividef(1.0f, l0);
        float r1 = __fdividef(1.0f, l1);

        int row = bt * NSEQ + m0 + mt * 16 + (lane >> 2);
        int col = h * HD + (lane & 3) * 2;
        *(float2*)&g_att[row * DMODEL + col]       = make_float2(o[mt][0] * r0, o[mt][1] * r0);
        *(float2*)&g_att[(row + 8) * DMODEL + col] = make_float2(o[mt][2] * r1, o[mt][3] * r1);
    }
}

// ---------------------------------------------------------------------------
// Kernel 3: out = relu(att @ W10 + b10) @ W11 + b11, f32x2.
// ---------------------------------------------------------------------------
__global__ __launch_bounds__(128) void proj_kernel(
    const float* __restrict__ W10, const float* __restrict__ b10,
    const float* __restrict__ W11, const float* __restrict__ b11,
    float* __restrict__ out)
{
    __shared__ __align__(16) float sW10T[64][68];
    __shared__ __align__(16) float sW11T[64][68];
    __shared__ float sb10[64], sb11[64];

    const int tid = threadIdx.x;
    for (int e = tid; e < 4096; e += 128) {
        int i = e >> 6, j = e & 63;
        sW10T[j][i] = W10[e];
        sW11T[j][i] = W11[e];
    }
    if (tid < 64) { sb10[tid] = b10[tid]; sb11[tid] = b11[tid]; }
    __syncthreads();

    const int row = blockIdx.x * 128 + tid;
    ulonglong2 xr[16];
    {
        const ulonglong2* xg = (const ulonglong2*)(g_att + row * DMODEL);
        #pragma unroll
        for (int q = 0; q < 16; q++) xr[q] = xg[q];
    }

    float hbuf[64];
    #pragma unroll 4
    for (int j = 0; j < 64; j++) {
        u64 hp = 0ull;
        const ulonglong2* w = (const ulonglong2*)&sW10T[j][0];
        #pragma unroll
        for (int q = 0; q < 16; q++) {
            ulonglong2 wv = w[q];
            hp = f2fma(xr[q].x, wv.x, hp);
            hp = f2fma(xr[q].y, wv.y, hp);
        }
        float a, b; upk(hp, a, b);
        hbuf[j] = fmaxf(a + b + sb10[j], 0.0f);
    }

    u64 hp2[32];
    #pragma unroll
    for (int t = 0; t < 32; t++) hp2[t] = pk2(hbuf[2 * t], hbuf[2 * t + 1]);

    float* orow = out + row * DMODEL;
    #pragma unroll 1
    for (int jq = 0; jq < 16; jq++) {
        float ob[4];
        #pragma unroll
        for (int jj = 0; jj < 4; jj++) {
            int j = jq * 4 + jj;
            u64 yp = 0ull;
            const ulonglong2* w = (const ulonglong2*)&sW11T[j][0];
            #pragma unroll
            for (int q = 0; q < 16; q++) {
                ulonglong2 wv = w[q];
                yp = f2fma(hp2[2 * q], wv.x, yp);
                yp = f2fma(hp2[2 * q + 1], wv.y, yp);
            }
            float a, b; upk(yp, a, b);
            ob[jj] = a + b + sb11[j];
        }
        *(float4*)&orow[jq * 4] = make_float4(ob[0], ob[1], ob[2], ob[3]);
    }
}

// ---------------------------------------------------------------------------
extern "C" void kernel_launch(void* const* d_in, const int* in_sizes, int n_in,
                              void* d_out, int out_size)
{
    const float* X   = (const float*)d_in[0];
    const float* STE = (const float*)d_in[1];
    const float* W7  = (const float*)d_in[2];
    const float* b7  = (const float*)d_in[3];
    const float* W8  = (const float*)d_in[4];
    const float* b8  = (const float*)d_in[5];
    const float* W9  = (const float*)d_in[6];
    const float* b9  = (const float*)d_in[7];
    const float* W10 = (const float*)d_in[8];
    const float* b10 = (const float*)d_in[9];
    const float* W11 = (const float*)d_in[10];
    const float* b11 = (const float*)d_in[11];
    float* out = (float*)d_out;

    qkv_kernel<<<dim3(TOKENS / 128, 3), 256>>>(X, STE, W7, b7, W8, b8, W9, b9);
    attn_kernel<<<dim3(NBT, KH), 256>>>();
    proj_kernel<<<TOKENS / 128, 128>>>(W10, b10, W11, b11, out);
}

// round 6
// speedup vs baseline: 2.2576x; 1.2814x over previous
#include <cuda_runtime.h>

// Problem constants
#define NBT   96      // B*T
#define NSEQ  512     // N
#define DMODEL 64
#define KH    8
#define HD    8
#define TOKENS (NBT * NSEQ)   // 49152

typedef unsigned long long u64;
typedef unsigned int u32;

// Scratch: q,k,v row-major [h][bt][n][d]; att [tok][64]
__device__ float g_q[KH * NBT * NSEQ * HD];
__device__ float g_k[KH * NBT * NSEQ * HD];
__device__ float g_v[KH * NBT * NSEQ * HD];
__device__ float g_att[TOKENS * DMODEL];

// ---------------- f32x2 packed-pair primitives ----------------
__device__ __forceinline__ u64 pk2(float a, float b) {
    u64 r; asm("mov.b64 %0, {%1,%2};" : "=l"(r) : "f"(a), "f"(b)); return r;
}
__device__ __forceinline__ void upk(u64 v, float& a, float& b) {
    asm("mov.b64 {%0,%1}, %2;" : "=f"(a), "=f"(b) : "l"(v));
}
__device__ __forceinline__ u64 f2fma(u64 a, u64 b, u64 c) {
    u64 d; asm("fma.rn.f32x2 %0, %1, %2, %3;" : "=l"(d) : "l"(a), "l"(b), "l"(c)); return d;
}
__device__ __forceinline__ u64 f2add(u64 a, u64 b) {
    u64 d; asm("add.rn.f32x2 %0, %1, %2;" : "=l"(d) : "l"(a), "l"(b)); return d;
}

// Packed 2^x of two fp32 lanes, x >= -0.5 (log2-domain scores, nonneg + eps).
__device__ __forceinline__ u64 exp2pk_bits(u64 x) {
    const u64 MAGIC  = pk2(12582912.0f, 12582912.0f);
    const u64 NMAGIC = pk2(-12582912.0f, -12582912.0f);
    const u64 NEG1   = pk2(-1.0f, -1.0f);
    const u64 C4     = pk2(9.6181291e-3f, 9.6181291e-3f);
    const u64 C3     = pk2(5.5504109e-2f, 5.5504109e-2f);
    const u64 C2     = pk2(2.4022651e-1f, 2.4022651e-1f);
    const u64 C1     = pk2(6.9314718e-1f, 6.9314718e-1f);
    const u64 ONE    = pk2(1.0f, 1.0f);

    u64 t = f2add(x, MAGIC);
    float ta, tb; upk(t, ta, tb);
    u64 r = f2add(t, NMAGIC);
    u64 g = f2fma(r, NEG1, x);          // g = x - rint(x)
    u64 p = f2fma(C4, g, C3);
    p = f2fma(p, g, C2);
    p = f2fma(p, g, C1);
    p = f2fma(p, g, ONE);               // p = 2^g
    float pa, pb; upk(p, pa, pb);
    u32 ia = __float_as_uint(pa) + (__float_as_uint(ta) << 23);
    u32 ib = __float_as_uint(pb) + (__float_as_uint(tb) << 23);
    return pk2(__uint_as_float(ia), __uint_as_float(ib));
}

// ---------------- bf16 split helpers ----------------
// pack {lo16 = bf16(x0), hi16 = bf16(x1)}  (low half = lower k index)
__device__ __forceinline__ u32 cvt_bf2(float x1, float x0) {
    u32 r; asm("cvt.rn.bf16x2.f32 %0, %1, %2;" : "=r"(r) : "f"(x1), "f"(x0)); return r;
}
__device__ __forceinline__ float bflo(u32 p) { return __uint_as_float(p << 16); }
__device__ __forceinline__ float bfhi(u32 p) { return __uint_as_float(p & 0xffff0000u); }
__device__ __forceinline__ void split2(float x0, float x1, u32& hp, u32& lp) {
    hp = cvt_bf2(x1, x0);
    lp = cvt_bf2(x1 - bfhi(hp), x0 - bflo(hp));
}

// m16n8k8 bf16 MMA, f32 accumulate, row.col
__device__ __forceinline__ void mma8(float (&d)[4], u32 a0, u32 a1, u32 b) {
    asm("mma.sync.aligned.m16n8k8.row.col.f32.bf16.bf16.f32 "
        "{%0,%1,%2,%3},{%4,%5},{%6},{%0,%1,%2,%3};"
        : "+f"(d[0]), "+f"(d[1]), "+f"(d[2]), "+f"(d[3])
        : "r"(a0), "r"(a1), "r"(b));
}

// B-frag smem pad: index (k2)*72 + n  -> LDS banks 8*(lane&3)+(lane>>2), all 32 distinct
#define WPAD 72

// ---------------------------------------------------------------------------
// Kernel 1: fused QKV projection on tensor cores (3-term bf16 split).
// grid (384, 3), 256 threads (8 warps); block tile 128 rows x 64 cols, K=128.
// W staged to smem as bf16 hi/lo k-pairs; A fragments straight from gmem.
// All outputs row-major [h][bt][n][d].
// ---------------------------------------------------------------------------
__global__ __launch_bounds__(256) void qkv_kernel(
    const float* __restrict__ X, const float* __restrict__ STE,
    const float* __restrict__ W7, const float* __restrict__ b7,
    const float* __restrict__ W8, const float* __restrict__ b8,
    const float* __restrict__ W9, const float* __restrict__ b9)
{
    __shared__ __align__(16) u32 swh[64 * WPAD];   // W hi pairs [k2][n]
    __shared__ __align__(16) u32 swl[64 * WPAD];   // W lo pairs

    const int mat = blockIdx.y;
    const float* W  = (mat == 0) ? W7 : (mat == 1) ? W8 : W9;
    const float* bv = (mat == 0) ? b7 : (mat == 1) ? b8 : b9;
    float* gout     = (mat == 0) ? g_q : (mat == 1) ? g_k : g_v;

    const int tid  = threadIdx.x;
    const int lane = tid & 31;
    const int warp = tid >> 5;
    const int row0 = blockIdx.x * 128;
    const int bt   = row0 >> 9;
    const int n0b  = row0 & 511;
    const int gr   = lane >> 2;
    const int kc   = lane & 3;

    // stage W as split pairs over k
    #pragma unroll
    for (int e = 0; e < 16; e++) {
        int idx = e * 256 + tid;          // 4096 pairs
        int k2 = idx >> 6, n = idx & 63;
        float w0 = W[(2 * k2) * 64 + n];
        float w1 = W[(2 * k2 + 1) * 64 + n];
        u32 hp, lp;
        split2(w0, w1, hp, lp);
        swh[k2 * WPAD + n] = hp;
        swl[k2 * WPAD + n] = lp;
    }
    __syncthreads();

    float c[8][4];
    #pragma unroll
    for (int nt = 0; nt < 8; nt++)
        #pragma unroll
        for (int e = 0; e < 4; e++) c[nt][e] = 0.0f;

    const int r0 = row0 + warp * 16 + gr;

    #pragma unroll 1
    for (int ks = 0; ks < 16; ks++) {
        const float* src = (ks < 8) ? X : STE;
        const int kk = (ks & 7) * 8 + kc * 2;
        float2 f0 = *(const float2*)(src + r0 * 64 + kk);
        float2 f1 = *(const float2*)(src + (r0 + 8) * 64 + kk);
        u32 ah0, al0, ah1, al1;
        split2(f0.x, f0.y, ah0, al0);
        split2(f1.x, f1.y, ah1, al1);

        const u32* bh = &swh[(ks * 4 + kc) * WPAD + gr];
        const u32* bl = &swl[(ks * 4 + kc) * WPAD + gr];
        #pragma unroll
        for (int nt = 0; nt < 8; nt++) {
            u32 wbh = bh[nt * 8];
            u32 wbl = bl[nt * 8];
            mma8(c[nt], ah0, ah1, wbh);
            mma8(c[nt], ah0, ah1, wbl);
            mma8(c[nt], al0, al1, wbh);
        }
    }

    // epilogue: bias + relu, row-major [h][bt][n][d]  (head == nt)
    const int n_lo = n0b + warp * 16 + gr;   // seq index for c0,c1 rows
    #pragma unroll
    for (int nt = 0; nt < 8; nt++) {
        const int d0 = kc * 2;
        float bx = bv[nt * 8 + d0], by = bv[nt * 8 + d0 + 1];
        float2 oA = make_float2(fmaxf(c[nt][0] + bx, 0.0f), fmaxf(c[nt][1] + by, 0.0f));
        float2 oB = make_float2(fmaxf(c[nt][2] + bx, 0.0f), fmaxf(c[nt][3] + by, 0.0f));
        float* dst = &gout[(((nt * NBT) + bt) * NSEQ + n_lo) * HD + d0];
        *(float2*)dst              = oA;
        *(float2*)(dst + 8 * HD)   = oB;
    }
}

// ---------------------------------------------------------------------------
// Kernel 2: attention per (bt, head) on tensor cores; V row-major staging;
// phase-batched inner loop. grid (96, 8), 256 threads.
// ---------------------------------------------------------------------------
__global__ __launch_bounds__(256) void attn_kernel()
{
    __shared__ __align__(16) u32 skh[NSEQ * 4];       // K hi pairs [j][c]
    __shared__ __align__(16) u32 skl[NSEQ * 4];
    __shared__ __align__(16) u32 svh[(NSEQ / 2) * 8]; // V hi pairs [j2][d]
    __shared__ __align__(16) u32 svl[(NSEQ / 2) * 8];

    const int bt   = blockIdx.x;
    const int h    = blockIdx.y;
    const int tid  = threadIdx.x;
    const int lane = tid & 31;
    const int warp = tid >> 5;
    const int base = (h * NBT + bt) * NSEQ * HD;

    // stage K (row-major [j][d]) -> bf16 hi/lo pairs over d
    #pragma unroll
    for (int rr = 0; rr < 2; rr++) {
        int r = tid + rr * 256;
        const float4* kp = (const float4*)(g_k + base + r * 8);
        float4 f0 = kp[0], f1 = kp[1];
        u32 h0, l0, h1, l1, h2, l2, h3, l3;
        split2(f0.x, f0.y, h0, l0);
        split2(f0.z, f0.w, h1, l1);
        split2(f1.x, f1.y, h2, l2);
        split2(f1.z, f1.w, h3, l3);
        *(uint4*)&skh[r * 4] = make_uint4(h0, h1, h2, h3);
        *(uint4*)&skl[r * 4] = make_uint4(l0, l1, l2, l3);
    }

    // stage V (row-major [j][d]) -> pairs over j at fixed d
    #pragma unroll
    for (int rep = 0; rep < 2; rep++) {
        int t = rep * 256 + tid;
        int j2 = t & 255, dg = t >> 8;        // dg: d group (0 -> d0..3, 1 -> d4..7)
        const float* vb = g_v + base + (2 * j2) * 8 + dg * 4;
        float4 f0 = *(const float4*)vb;           // row 2*j2
        float4 f1 = *(const float4*)(vb + 8);     // row 2*j2+1
        u32 hp, lp;
        split2(f0.x, f1.x, hp, lp); svh[j2 * 8 + dg * 4 + 0] = hp; svl[j2 * 8 + dg * 4 + 0] = lp;
        split2(f0.y, f1.y, hp, lp); svh[j2 * 8 + dg * 4 + 1] = hp; svl[j2 * 8 + dg * 4 + 1] = lp;
        split2(f0.z, f1.z, hp, lp); svh[j2 * 8 + dg * 4 + 2] = hp; svl[j2 * 8 + dg * 4 + 2] = lp;
        split2(f0.w, f1.w, hp, lp); svh[j2 * 8 + dg * 4 + 3] = hp; svl[j2 * 8 + dg * 4 + 3] = lp;
    }

    // Q A-fragments, log2-domain pre-scale, hi/lo split
    const float qscale = 0.35355339059327373f * 1.4426950408889634f;
    u32 qh[4][2], ql[4][2];
    const int m0 = warp * 64;
    {
        const float* qb = g_q + base;
        #pragma unroll
        for (int mt = 0; mt < 4; mt++) {
            int r = m0 + mt * 16 + (lane >> 2);
            float2 f0 = *(const float2*)(qb + r * 8 + (lane & 3) * 2);
            float2 f1 = *(const float2*)(qb + (r + 8) * 8 + (lane & 3) * 2);
            split2(f0.x * qscale, f0.y * qscale, qh[mt][0], ql[mt][0]);
            split2(f1.x * qscale, f1.y * qscale, qh[mt][1], ql[mt][1]);
        }
    }
    __syncthreads();

    float o[4][4];
    #pragma unroll
    for (int mt = 0; mt < 4; mt++)
        #pragma unroll
        for (int e = 0; e < 4; e++) o[mt][e] = 0.0f;
    u64 lA[4], lB[4];
    #pragma unroll
    for (int mt = 0; mt < 4; mt++) { lA[mt] = 0ull; lB[mt] = 0ull; }

    const int vb_idx = (lane & 3) * 8 + (lane >> 2);

    #pragma unroll 1
    for (int j0 = 0; j0 < NSEQ; j0 += 8) {
        u32 bkh = skh[j0 * 4 + lane];
        u32 bkl = skl[j0 * 4 + lane];
        u32 bvh = svh[(j0 >> 1) * 8 + vb_idx];
        u32 bvl = svl[(j0 >> 1) * 8 + vb_idx];

        // phase 1: all score MMAs
        float s[4][4];
        #pragma unroll
        for (int mt = 0; mt < 4; mt++) {
            s[mt][0] = s[mt][1] = s[mt][2] = s[mt][3] = 0.0f;
            mma8(s[mt], qh[mt][0], qh[mt][1], bkh);
            mma8(s[mt], qh[mt][0], qh[mt][1], bkl);
            mma8(s[mt], ql[mt][0], ql[mt][1], bkh);
        }

        // phase 2: all exps
        u64 p01[4], p23[4];
        #pragma unroll
        for (int mt = 0; mt < 4; mt++) {
            p01[mt] = exp2pk_bits(pk2(s[mt][0], s[mt][1]));
            p23[mt] = exp2pk_bits(pk2(s[mt][2], s[mt][3]));
            lA[mt] = f2add(lA[mt], p01[mt]);
            lB[mt] = f2add(lB[mt], p23[mt]);
        }

        // phase 3: all PV MMAs
        #pragma unroll
        for (int mt = 0; mt < 4; mt++) {
            float p0, p1, p2, p3;
            upk(p01[mt], p0, p1);
            upk(p23[mt], p2, p3);
            u32 pah, pal, pbh, pbl;
            split2(p0, p1, pah, pal);
            split2(p2, p3, pbh, pbl);
            mma8(o[mt], pah, pbh, bvh);
            mma8(o[mt], pah, pbh, bvl);
            mma8(o[mt], pal, pbl, bvh);
        }
    }

    // normalize and write
    #pragma unroll
    for (int mt = 0; mt < 4; mt++) {
        float a, b;
        upk(lA[mt], a, b);
        float l0 = a + b;
        upk(lB[mt], a, b);
        float l1 = a + b;
        l0 += __shfl_xor_sync(0xffffffffu, l0, 1);
        l0 += __shfl_xor_sync(0xffffffffu, l0, 2);
        l1 += __shfl_xor_sync(0xffffffffu, l1, 1);
        l1 += __shfl_xor_sync(0xffffffffu, l1, 2);
        float r0 = __fdividef(1.0f, l0);
        float r1 = __fdividef(1.0f, l1);

        int row = bt * NSEQ + m0 + mt * 16 + (lane >> 2);
        int col = h * HD + (lane & 3) * 2;
        *(float2*)&g_att[row * DMODEL + col]       = make_float2(o[mt][0] * r0, o[mt][1] * r0);
        *(float2*)&g_att[(row + 8) * DMODEL + col] = make_float2(o[mt][2] * r1, o[mt][3] * r1);
    }
}

// ---------------------------------------------------------------------------
// Kernel 3: out = relu(att @ W10 + b10) @ W11 + b11 on tensor cores.
// GEMM1's C fragment layout == GEMM2's A fragment layout -> chained in regs.
// grid 384, 256 threads, tile 128 rows.
// ---------------------------------------------------------------------------
__global__ __launch_bounds__(256) void proj_kernel(
    const float* __restrict__ W10, const float* __restrict__ b10,
    const float* __restrict__ W11, const float* __restrict__ b11,
    float* __restrict__ out)
{
    __shared__ __align__(16) u32 sw10h[32 * WPAD];
    __shared__ __align__(16) u32 sw10l[32 * WPAD];
    __shared__ __align__(16) u32 sw11h[32 * WPAD];
    __shared__ __align__(16) u32 sw11l[32 * WPAD];

    const int tid  = threadIdx.x;
    const int lane = tid & 31;
    const int warp = tid >> 5;
    const int gr   = lane >> 2;
    const int kc   = lane & 3;

    // stage both weights as split pairs
    #pragma unroll
    for (int e = 0; e < 8; e++) {
        int idx = e * 256 + tid;          // 2048 pairs each
        int k2 = idx >> 6, n = idx & 63;
        u32 hp, lp;
        split2(W10[(2 * k2) * 64 + n], W10[(2 * k2 + 1) * 64 + n], hp, lp);
        sw10h[k2 * WPAD + n] = hp;
        sw10l[k2 * WPAD + n] = lp;
        split2(W11[(2 * k2) * 64 + n], W11[(2 * k2 + 1) * 64 + n], hp, lp);
        sw11h[k2 * WPAD + n] = hp;
        sw11l[k2 * WPAD + n] = lp;
    }
    __syncthreads();

    const int r0 = blockIdx.x * 128 + warp * 16 + gr;

    // GEMM1: c1 = att @ W10
    float c1[8][4];
    #pragma unroll
    for (int nt = 0; nt < 8; nt++)
        #pragma unroll
        for (int e = 0; e < 4; e++) c1[nt][e] = 0.0f;

    #pragma unroll
    for (int ks = 0; ks < 8; ks++) {
        const int kk = ks * 8 + kc * 2;
        float2 f0 = *(const float2*)(g_att + r0 * 64 + kk);
        float2 f1 = *(const float2*)(g_att + (r0 + 8) * 64 + kk);
        u32 ah0, al0, ah1, al1;
        split2(f0.x, f0.y, ah0, al0);
        split2(f1.x, f1.y, ah1, al1);
        const u32* bh = &sw10h[(ks * 4 + kc) * WPAD + gr];
        const u32* bl = &sw10l[(ks * 4 + kc) * WPAD + gr];
        #pragma unroll
        for (int nt = 0; nt < 8; nt++) {
            u32 wbh = bh[nt * 8];
            u32 wbl = bl[nt * 8];
            mma8(c1[nt], ah0, ah1, wbh);
            mma8(c1[nt], ah0, ah1, wbl);
            mma8(c1[nt], al0, al1, wbh);
        }
    }

    // bias + relu in fragment form
    #pragma unroll
    for (int nt = 0; nt < 8; nt++) {
        float bx = b10[nt * 8 + kc * 2], by = b10[nt * 8 + kc * 2 + 1];
        c1[nt][0] = fmaxf(c1[nt][0] + bx, 0.0f);
        c1[nt][1] = fmaxf(c1[nt][1] + by, 0.0f);
        c1[nt][2] = fmaxf(c1[nt][2] + bx, 0.0f);
        c1[nt][3] = fmaxf(c1[nt][3] + by, 0.0f);
    }

    // GEMM2: c2 = c1 @ W11  (c1 C-frag == A-frag layout, ks == nt of GEMM1)
    float c2[8][4];
    #pragma unroll
    for (int nt = 0; nt < 8; nt++)
        #pragma unroll
        for (int e = 0; e < 4; e++) c2[nt][e] = 0.0f;

    #pragma unroll
    for (int ks = 0; ks < 8; ks++) {
        u32 ah0, al0, ah1, al1;
        split2(c1[ks][0], c1[ks][1], ah0, al0);
        split2(c1[ks][2], c1[ks][3], ah1, al1);
        const u32* bh = &sw11h[(ks * 4 + kc) * WPAD + gr];
        const u32* bl = &sw11l[(ks * 4 + kc) * WPAD + gr];
        #pragma unroll
        for (int nt = 0; nt < 8; nt++) {
            u32 wbh = bh[nt * 8];
            u32 wbl = bl[nt * 8];
            mma8(c2[nt], ah0, ah1, wbh);
            mma8(c2[nt], ah0, ah1, wbl);
            mma8(c2[nt], al0, al1, wbh);
        }
    }

    // epilogue: + b11, write
    #pragma unroll
    for (int nt = 0; nt < 8; nt++) {
        float bx = b11[nt * 8 + kc * 2], by = b11[nt * 8 + kc * 2 + 1];
        float* dst = out + r0 * 64 + nt * 8 + kc * 2;
        *(float2*)dst               = make_float2(c2[nt][0] + bx, c2[nt][1] + by);
        *(float2*)(dst + 8 * 64)    = make_float2(c2[nt][2] + bx, c2[nt][3] + by);
    }
}

// ---------------------------------------------------------------------------
extern "C" void kernel_launch(void* const* d_in, const int* in_sizes, int n_in,
                              void* d_out, int out_size)
{
    const float* X   = (const float*)d_in[0];
    const float* STE = (const float*)d_in[1];
    const float* W7  = (const float*)d_in[2];
    const float* b7  = (const float*)d_in[3];
    const float* W8  = (const float*)d_in[4];
    const float* b8  = (const float*)d_in[5];
    const float* W9  = (const float*)d_in[6];
    const float* b9  = (const float*)d_in[7];
    const float* W10 = (const float*)d_in[8];
    const float* b10 = (const float*)d_in[9];
    const float* W11 = (const float*)d_in[10];
    const float* b11 = (const float*)d_in[11];
    float* out = (float*)d_out;

    qkv_kernel<<<dim3(TOKENS / 128, 3), 256>>>(X, STE, W7, b7, W8, b8, W9, b9);
    attn_kernel<<<dim3(NBT, KH), 256>>>();
    proj_kernel<<<TOKENS / 128, 256>>>(W10, b10, W11, b11, out);
}

// round 7
// speedup vs baseline: 3.1715x; 1.4048x over previous
#include <cuda_runtime.h>

// Problem constants
#define NBT   96      // B*T
#define NSEQ  512     // N
#define DMODEL 64
#define KH    8
#define HD    8
#define TOKENS (NBT * NSEQ)   // 49152

typedef unsigned long long u64;
typedef unsigned int u32;

// Scratch: q,k,v row-major [h][bt][n][d]; att [tok][64]
__device__ float g_q[KH * NBT * NSEQ * HD];
__device__ float g_k[KH * NBT * NSEQ * HD];
__device__ float g_v[KH * NBT * NSEQ * HD];
__device__ float g_att[TOKENS * DMODEL];

// ---------------- helpers ----------------
__device__ __forceinline__ float ex2(float x) {
    float y; asm("ex2.approx.f32 %0, %1;" : "=f"(y) : "f"(x)); return y;
}

// pack {lo16 = bf16(x0), hi16 = bf16(x1)}
__device__ __forceinline__ u32 cvt_bf2(float x1, float x0) {
    u32 r; asm("cvt.rn.bf16x2.f32 %0, %1, %2;" : "=r"(r) : "f"(x1), "f"(x0)); return r;
}
__device__ __forceinline__ float bflo(u32 p) { return __uint_as_float(p << 16); }
__device__ __forceinline__ float bfhi(u32 p) { return __uint_as_float(p & 0xffff0000u); }
__device__ __forceinline__ void split2(float x0, float x1, u32& hp, u32& lp) {
    hp = cvt_bf2(x1, x0);
    lp = cvt_bf2(x1 - bfhi(hp), x0 - bflo(hp));
}

// m16n8k8 bf16 MMA, f32 accumulate, row.col
__device__ __forceinline__ void mma8(float (&d)[4], u32 a0, u32 a1, u32 b) {
    asm("mma.sync.aligned.m16n8k8.row.col.f32.bf16.bf16.f32 "
        "{%0,%1,%2,%3},{%4,%5},{%6},{%0,%1,%2,%3};"
        : "+f"(d[0]), "+f"(d[1]), "+f"(d[2]), "+f"(d[3])
        : "r"(a0), "r"(a1), "r"(b));
}
// m16n8k16 bf16 MMA
__device__ __forceinline__ void mma16(float (&d)[4], u32 a0, u32 a1, u32 a2, u32 a3,
                                      u32 b0, u32 b1) {
    asm("mma.sync.aligned.m16n8k16.row.col.f32.bf16.bf16.f32 "
        "{%0,%1,%2,%3},{%4,%5,%6,%7},{%8,%9},{%0,%1,%2,%3};"
        : "+f"(d[0]), "+f"(d[1]), "+f"(d[2]), "+f"(d[3])
        : "r"(a0), "r"(a1), "r"(a2), "r"(a3), "r"(b0), "r"(b1));
}

// B-frag smem pad: (k2)*72 + n -> conflict-free B-frag LDS
#define WPAD 72

// ---------------------------------------------------------------------------
// Kernel 1: fused QKV projection on tensor cores (3-term split, k16-folded).
// grid (384, 3), 256 threads; block tile 128 rows x 64 cols, K=128.
// Outputs row-major [h][bt][n][d].
// ---------------------------------------------------------------------------
__global__ __launch_bounds__(256) void qkv_kernel(
    const float* __restrict__ X, const float* __restrict__ STE,
    const float* __restrict__ W7, const float* __restrict__ b7,
    const float* __restrict__ W8, const float* __restrict__ b8,
    const float* __restrict__ W9, const float* __restrict__ b9)
{
    __shared__ __align__(16) u32 swh[64 * WPAD];   // W hi pairs [k2][n]
    __shared__ __align__(16) u32 swl[64 * WPAD];   // W lo pairs

    const int mat = blockIdx.y;
    const float* W  = (mat == 0) ? W7 : (mat == 1) ? W8 : W9;
    const float* bv = (mat == 0) ? b7 : (mat == 1) ? b8 : b9;
    float* gout     = (mat == 0) ? g_q : (mat == 1) ? g_k : g_v;

    const int tid  = threadIdx.x;
    const int lane = tid & 31;
    const int warp = tid >> 5;
    const int row0 = blockIdx.x * 128;
    const int bt   = row0 >> 9;
    const int n0b  = row0 & 511;
    const int gr   = lane >> 2;
    const int kc   = lane & 3;

    #pragma unroll
    for (int e = 0; e < 16; e++) {
        int idx = e * 256 + tid;
        int k2 = idx >> 6, n = idx & 63;
        float w0 = W[(2 * k2) * 64 + n];
        float w1 = W[(2 * k2 + 1) * 64 + n];
        u32 hp, lp;
        split2(w0, w1, hp, lp);
        swh[k2 * WPAD + n] = hp;
        swl[k2 * WPAD + n] = lp;
    }
    __syncthreads();

    float c[8][4];
    #pragma unroll
    for (int nt = 0; nt < 8; nt++)
        #pragma unroll
        for (int e = 0; e < 4; e++) c[nt][e] = 0.0f;

    const int r0 = row0 + warp * 16 + gr;

    #pragma unroll 1
    for (int ks = 0; ks < 16; ks++) {
        const float* src = (ks < 8) ? X : STE;
        const int kk = (ks & 7) * 8 + kc * 2;
        float2 f0 = *(const float2*)(src + r0 * 64 + kk);
        float2 f1 = *(const float2*)(src + (r0 + 8) * 64 + kk);
        u32 ah0, al0, ah1, al1;
        split2(f0.x, f0.y, ah0, al0);
        split2(f1.x, f1.y, ah1, al1);

        const u32* bh = &swh[(ks * 4 + kc) * WPAD + gr];
        const u32* bl = &swl[(ks * 4 + kc) * WPAD + gr];
        #pragma unroll
        for (int nt = 0; nt < 8; nt++) {
            u32 wbh = bh[nt * 8];
            u32 wbl = bl[nt * 8];
            mma16(c[nt], ah0, ah1, al0, al1, wbh, wbh);  // ah*bh + al*bh
            mma8(c[nt], ah0, ah1, wbl);                  // ah*bl
        }
    }

    const int n_lo = n0b + warp * 16 + gr;
    #pragma unroll
    for (int nt = 0; nt < 8; nt++) {
        const int d0 = kc * 2;
        float bx = bv[nt * 8 + d0], by = bv[nt * 8 + d0 + 1];
        float2 oA = make_float2(fmaxf(c[nt][0] + bx, 0.0f), fmaxf(c[nt][1] + by, 0.0f));
        float2 oB = make_float2(fmaxf(c[nt][2] + bx, 0.0f), fmaxf(c[nt][3] + by, 0.0f));
        float* dst = &gout[(((nt * NBT) + bt) * NSEQ + n_lo) * HD + d0];
        *(float2*)dst            = oA;
        *(float2*)(dst + 8 * HD) = oB;
    }
}

// ---------------------------------------------------------------------------
// Kernel 2: attention per (bt, head); MUFU exp; 16-j steps; k16-folded MMAs.
// grid (96, 8), 256 threads (8 warps), warp owns 64 query rows.
// ---------------------------------------------------------------------------
__global__ __launch_bounds__(256) void attn_kernel()
{
    __shared__ __align__(16) u32 skh[NSEQ * 4];       // K hi pairs [j][c]
    __shared__ __align__(16) u32 skl[NSEQ * 4];
    __shared__ __align__(16) u32 svh[(NSEQ / 2) * 8]; // V hi pairs [j2][d]
    __shared__ __align__(16) u32 svl[(NSEQ / 2) * 8];

    const int bt   = blockIdx.x;
    const int h    = blockIdx.y;
    const int tid  = threadIdx.x;
    const int lane = tid & 31;
    const int warp = tid >> 5;
    const int base = (h * NBT + bt) * NSEQ * HD;

    // stage K -> bf16 hi/lo pairs over d
    #pragma unroll
    for (int rr = 0; rr < 2; rr++) {
        int r = tid + rr * 256;
        const float4* kp = (const float4*)(g_k + base + r * 8);
        float4 f0 = kp[0], f1 = kp[1];
        u32 h0, l0, h1, l1, h2, l2, h3, l3;
        split2(f0.x, f0.y, h0, l0);
        split2(f0.z, f0.w, h1, l1);
        split2(f1.x, f1.y, h2, l2);
        split2(f1.z, f1.w, h3, l3);
        *(uint4*)&skh[r * 4] = make_uint4(h0, h1, h2, h3);
        *(uint4*)&skl[r * 4] = make_uint4(l0, l1, l2, l3);
    }

    // stage V -> pairs over j at fixed d
    #pragma unroll
    for (int rep = 0; rep < 2; rep++) {
        int t = rep * 256 + tid;
        int j2 = t & 255, dg = t >> 8;
        const float* vb = g_v + base + (2 * j2) * 8 + dg * 4;
        float4 f0 = *(const float4*)vb;
        float4 f1 = *(const float4*)(vb + 8);
        u32 hp, lp;
        split2(f0.x, f1.x, hp, lp); svh[j2 * 8 + dg * 4 + 0] = hp; svl[j2 * 8 + dg * 4 + 0] = lp;
        split2(f0.y, f1.y, hp, lp); svh[j2 * 8 + dg * 4 + 1] = hp; svl[j2 * 8 + dg * 4 + 1] = lp;
        split2(f0.z, f1.z, hp, lp); svh[j2 * 8 + dg * 4 + 2] = hp; svl[j2 * 8 + dg * 4 + 2] = lp;
        split2(f0.w, f1.w, hp, lp); svh[j2 * 8 + dg * 4 + 3] = hp; svl[j2 * 8 + dg * 4 + 3] = lp;
    }

    // Q A-fragments, log2-domain pre-scale, hi/lo split
    const float qscale = 0.35355339059327373f * 1.4426950408889634f;
    u32 qh[4][2], ql[4][2];
    const int m0 = warp * 64;
    {
        const float* qb = g_q + base;
        #pragma unroll
        for (int mt = 0; mt < 4; mt++) {
            int r = m0 + mt * 16 + (lane >> 2);
            float2 f0 = *(const float2*)(qb + r * 8 + (lane & 3) * 2);
            float2 f1 = *(const float2*)(qb + (r + 8) * 8 + (lane & 3) * 2);
            split2(f0.x * qscale, f0.y * qscale, qh[mt][0], ql[mt][0]);
            split2(f1.x * qscale, f1.y * qscale, qh[mt][1], ql[mt][1]);
        }
    }
    __syncthreads();

    float o[4][4];
    float l0[4], l1[4];
    #pragma unroll
    for (int mt = 0; mt < 4; mt++) {
        o[mt][0] = o[mt][1] = o[mt][2] = o[mt][3] = 0.0f;
        l0[mt] = 0.0f; l1[mt] = 0.0f;
    }

    const int vb_idx = (lane & 3) * 8 + (lane >> 2);

    #pragma unroll 1
    for (int j0 = 0; j0 < NSEQ; j0 += 16) {
        u32 bkh0 = skh[j0 * 4 + lane];
        u32 bkl0 = skl[j0 * 4 + lane];
        u32 bkh1 = skh[(j0 + 8) * 4 + lane];
        u32 bkl1 = skl[(j0 + 8) * 4 + lane];
        u32 bvh0 = svh[(j0 >> 1) * 8 + vb_idx];
        u32 bvl0 = svl[(j0 >> 1) * 8 + vb_idx];
        u32 bvh1 = svh[(j0 >> 1) * 8 + 32 + vb_idx];
        u32 bvl1 = svl[(j0 >> 1) * 8 + 32 + vb_idx];

        #pragma unroll
        for (int mt = 0; mt < 4; mt++) {
            // scores for two 8-j chunks (3-term split, k16-folded)
            float s0[4] = {0, 0, 0, 0}, s1[4] = {0, 0, 0, 0};
            mma16(s0, qh[mt][0], qh[mt][1], ql[mt][0], ql[mt][1], bkh0, bkh0);
            mma8(s0, qh[mt][0], qh[mt][1], bkl0);
            mma16(s1, qh[mt][0], qh[mt][1], ql[mt][0], ql[mt][1], bkh1, bkh1);
            mma8(s1, qh[mt][0], qh[mt][1], bkl1);

            // exp on MUFU pipe
            float p00 = ex2(s0[0]), p01 = ex2(s0[1]), p02 = ex2(s0[2]), p03 = ex2(s0[3]);
            float p10 = ex2(s1[0]), p11 = ex2(s1[1]), p12 = ex2(s1[2]), p13 = ex2(s1[3]);
            l0[mt] += (p00 + p01) + (p10 + p11);
            l1[mt] += (p02 + p03) + (p12 + p13);

            // split P, feed PV as k16 over 16 j
            u32 pah0, pal0, pbh0, pbl0, pah1, pal1, pbh1, pbl1;
            split2(p00, p01, pah0, pal0);
            split2(p02, p03, pbh0, pbl0);
            split2(p10, p11, pah1, pal1);
            split2(p12, p13, pbh1, pbl1);

            mma16(o[mt], pah0, pbh0, pah1, pbh1, bvh0, bvh1);
            mma16(o[mt], pah0, pbh0, pah1, pbh1, bvl0, bvl1);
            mma16(o[mt], pal0, pbl0, pal1, pbl1, bvh0, bvh1);
        }
    }

    // normalize and write
    #pragma unroll
    for (int mt = 0; mt < 4; mt++) {
        float a = l0[mt], b = l1[mt];
        a += __shfl_xor_sync(0xffffffffu, a, 1);
        a += __shfl_xor_sync(0xffffffffu, a, 2);
        b += __shfl_xor_sync(0xffffffffu, b, 1);
        b += __shfl_xor_sync(0xffffffffu, b, 2);
        float r0 = __fdividef(1.0f, a);
        float r1 = __fdividef(1.0f, b);

        int row = bt * NSEQ + m0 + mt * 16 + (lane >> 2);
        int col = h * HD + (lane & 3) * 2;
        *(float2*)&g_att[row * DMODEL + col]       = make_float2(o[mt][0] * r0, o[mt][1] * r0);
        *(float2*)&g_att[(row + 8) * DMODEL + col] = make_float2(o[mt][2] * r1, o[mt][3] * r1);
    }
}

// ---------------------------------------------------------------------------
// Kernel 3: out = relu(att @ W10 + b10) @ W11 + b11; k16-folded; GEMM1 C frag
// chains into GEMM2 A frag in registers. grid 384, 256 threads.
// ---------------------------------------------------------------------------
__global__ __launch_bounds__(256) void proj_kernel(
    const float* __restrict__ W10, const float* __restrict__ b10,
    const float* __restrict__ W11, const float* __restrict__ b11,
    float* __restrict__ out)
{
    __shared__ __align__(16) u32 sw10h[32 * WPAD];
    __shared__ __align__(16) u32 sw10l[32 * WPAD];
    __shared__ __align__(16) u32 sw11h[32 * WPAD];
    __shared__ __align__(16) u32 sw11l[32 * WPAD];

    const int tid  = threadIdx.x;
    const int lane = tid & 31;
    const int warp = tid >> 5;
    const int gr   = lane >> 2;
    const int kc   = lane & 3;

    #pragma unroll
    for (int e = 0; e < 8; e++) {
        int idx = e * 256 + tid;
        int k2 = idx >> 6, n = idx & 63;
        u32 hp, lp;
        split2(W10[(2 * k2) * 64 + n], W10[(2 * k2 + 1) * 64 + n], hp, lp);
        sw10h[k2 * WPAD + n] = hp;
        sw10l[k2 * WPAD + n] = lp;
        split2(W11[(2 * k2) * 64 + n], W11[(2 * k2 + 1) * 64 + n], hp, lp);
        sw11h[k2 * WPAD + n] = hp;
        sw11l[k2 * WPAD + n] = lp;
    }
    __syncthreads();

    const int r0 = blockIdx.x * 128 + warp * 16 + gr;

    float c1[8][4];
    #pragma unroll
    for (int nt = 0; nt < 8; nt++)
        #pragma unroll
        for (int e = 0; e < 4; e++) c1[nt][e] = 0.0f;

    #pragma unroll
    for (int ks = 0; ks < 8; ks++) {
        const int kk = ks * 8 + kc * 2;
        float2 f0 = *(const float2*)(g_att + r0 * 64 + kk);
        float2 f1 = *(const float2*)(g_att + (r0 + 8) * 64 + kk);
        u32 ah0, al0, ah1, al1;
        split2(f0.x, f0.y, ah0, al0);
        split2(f1.x, f1.y, ah1, al1);
        const u32* bh = &sw10h[(ks * 4 + kc) * WPAD + gr];
        const u32* bl = &sw10l[(ks * 4 + kc) * WPAD + gr];
        #pragma unroll
        for (int nt = 0; nt < 8; nt++) {
            u32 wbh = bh[nt * 8];
            u32 wbl = bl[nt * 8];
            mma16(c1[nt], ah0, ah1, al0, al1, wbh, wbh);
            mma8(c1[nt], ah0, ah1, wbl);
        }
    }

    #pragma unroll
    for (int nt = 0; nt < 8; nt++) {
        float bx = b10[nt * 8 + kc * 2], by = b10[nt * 8 + kc * 2 + 1];
        c1[nt][0] = fmaxf(c1[nt][0] + bx, 0.0f);
        c1[nt][1] = fmaxf(c1[nt][1] + by, 0.0f);
        c1[nt][2] = fmaxf(c1[nt][2] + bx, 0.0f);
        c1[nt][3] = fmaxf(c1[nt][3] + by, 0.0f);
    }

    float c2[8][4];
    #pragma unroll
    for (int nt = 0; nt < 8; nt++)
        #pragma unroll
        for (int e = 0; e < 4; e++) c2[nt][e] = 0.0f;

    #pragma unroll
    for (int ks = 0; ks < 8; ks++) {
        u32 ah0, al0, ah1, al1;
        split2(c1[ks][0], c1[ks][1], ah0, al0);
        split2(c1[ks][2], c1[ks][3], ah1, al1);
        const u32* bh = &sw11h[(ks * 4 + kc) * WPAD + gr];
        const u32* bl = &sw11l[(ks * 4 + kc) * WPAD + gr];
        #pragma unroll
        for (int nt = 0; nt < 8; nt++) {
            u32 wbh = bh[nt * 8];
            u32 wbl = bl[nt * 8];
            mma16(c2[nt], ah0, ah1, al0, al1, wbh, wbh);
            mma8(c2[nt], ah0, ah1, wbl);
        }
    }

    #pragma unroll
    for (int nt = 0; nt < 8; nt++) {
        float bx = b11[nt * 8 + kc * 2], by = b11[nt * 8 + kc * 2 + 1];
        float* dst = out + r0 * 64 + nt * 8 + kc * 2;
        *(float2*)dst            = make_float2(c2[nt][0] + bx, c2[nt][1] + by);
        *(float2*)(dst + 8 * 64) = make_float2(c2[nt][2] + bx, c2[nt][3] + by);
    }
}

// ---------------------------------------------------------------------------
extern "C" void kernel_launch(void* const* d_in, const int* in_sizes, int n_in,
                              void* d_out, int out_size)
{
    const float* X   = (const float*)d_in[0];
    const float* STE = (const float*)d_in[1];
    const float* W7  = (const float*)d_in[2];
    const float* b7  = (const float*)d_in[3];
    const float* W8  = (const float*)d_in[4];
    const float* b8  = (const float*)d_in[5];
    const float* W9  = (const float*)d_in[6];
    const float* b9  = (const float*)d_in[7];
    const float* W10 = (const float*)d_in[8];
    const float* b10 = (const float*)d_in[9];
    const float* W11 = (const float*)d_in[10];
    const float* b11 = (const float*)d_in[11];
    float* out = (float*)d_out;

    qkv_kernel<<<dim3(TOKENS / 128, 3), 256>>>(X, STE, W7, b7, W8, b8, W9, b9);
    attn_kernel<<<dim3(NBT, KH), 256>>>();
    proj_kernel<<<TOKENS / 128, 256>>>(W10, b10, W11, b11, out);
}